// round 2
// baseline (speedup 1.0000x reference)
#include <cuda_runtime.h>
#include <cuda_fp16.h>
#include <stdint.h>

#define TOK 16384
#define CDIM 768
#define NCDIM 3072
#define DFFDIM 3072

// ---------------- device scratch (static; no allocs allowed) ----------------
__device__ __half g_xh[(size_t)TOK * NCDIM];      // x in fp16            (100MB)
__device__ float  g_invr[TOK];
__device__ __half g_phit[32 * NCDIM];             // phi^T padded [32][3072]
__device__ __half g_w1t[(size_t)DFFDIM * CDIM];   // W1^T [3072][768]
__device__ __half g_w2t[(size_t)CDIM * DFFDIM];   // W2^T [768][3072]
__device__ float  g_mix[(size_t)TOK * 32];        // raw x@phi (pre-invr)
__device__ float  g_hpre[TOK * 4];
__device__ float  g_hpost[TOK * 4];
__device__ float  g_hres[TOK * 16];
__device__ __half g_xinh[(size_t)TOK * CDIM];     // pre-aggregated stream, fp16
__device__ __half g_hidh[(size_t)TOK * DFFDIM];   // gelu(x_in@W1+b1), fp16 (100MB)
__device__ float  g_fout[(size_t)TOK * CDIM];     // hidden@W2+b2, fp32

// ---------------- kernel 0: convert + transpose weights ----------------
__global__ void prep_kernel(const float* __restrict__ W1,
                            const float* __restrict__ W2,
                            const float* __restrict__ phi) {
    int i = blockIdx.x * blockDim.x + threadIdx.x;
    int stride = gridDim.x * blockDim.x;
    for (int idx = i; idx < DFFDIM * CDIM; idx += stride) {
        int n = idx / CDIM, k = idx % CDIM;
        g_w1t[idx] = __float2half(W1[(size_t)k * DFFDIM + n]);
    }
    for (int idx = i; idx < CDIM * DFFDIM; idx += stride) {
        int n = idx / DFFDIM, k = idx % DFFDIM;
        g_w2t[idx] = __float2half(W2[(size_t)k * CDIM + n]);
    }
    for (int idx = i; idx < 32 * NCDIM; idx += stride) {
        int j = idx / NCDIM, k = idx % NCDIM;
        g_phit[idx] = (j < 24) ? __float2half(phi[k * 24 + j]) : __float2half(0.0f);
    }
}

// ---------------- kernel 1: rms sumsq + fp32->fp16 convert ----------------
__global__ void sumsq_convert_kernel(const float* __restrict__ x) {
    int gw = (blockIdx.x * blockDim.x + threadIdx.x) >> 5;
    int lane = threadIdx.x & 31;
    if (gw >= TOK) return;
    const float4* row = (const float4*)(x + (size_t)gw * NCDIM);
    __half2* outrow = (__half2*)(g_xh + (size_t)gw * NCDIM);
    float ss = 0.f;
    #pragma unroll 4
    for (int i = lane; i < NCDIM / 4; i += 32) {
        float4 v = row[i];
        ss += v.x * v.x + v.y * v.y + v.z * v.z + v.w * v.w;
        outrow[2 * i]     = __floats2half2_rn(v.x, v.y);
        outrow[2 * i + 1] = __floats2half2_rn(v.z, v.w);
    }
    #pragma unroll
    for (int o = 16; o; o >>= 1) ss += __shfl_xor_sync(0xffffffffu, ss, o);
    if (lane == 0) g_invr[gw] = rsqrtf(ss / (float)NCDIM + 1e-6f);
}

// ---------------- mma.sync GEMM (fp16 in, fp32 acc) ----------------
#define CP_ASYNC16(dst, src) asm volatile("cp.async.cg.shared.global [%0], [%1], 16;\n" :: "r"(dst), "l"(src))
#define CP_COMMIT() asm volatile("cp.async.commit_group;\n" ::)
#define CP_WAIT(N_) asm volatile("cp.async.wait_group %0;\n" :: "n"(N_))

__device__ __forceinline__ float gelu_exact(float v) {
    return 0.5f * v * (1.0f + erff(v * 0.70710678118654752f));
}

// EPI 0: mix = x_h @ phi_t          (M=16384, N=32,  K=3072) -> g_mix (fp32, raw)
// EPI 1: hid = gelu(xin@W1 + b1)    (M=16384, N=3072,K=768)  -> g_hidh (fp16)
// EPI 2: fout = hid@W2 + b2         (M=16384, N=768, K=3072) -> g_fout (fp32)
template <int EPI>
__global__ void __launch_bounds__((EPI == 0) ? 128 : 256, 2)
gemm_mma(const float* __restrict__ bias) {
    constexpr int BM = 128, BK = 32;
    constexpr int BN  = (EPI == 0) ? 32 : 128;
    constexpr int WMQ = (EPI == 0) ? 4 : 2;
    constexpr int WNQ = (EPI == 0) ? 1 : 4;
    constexpr int THREADS = WMQ * WNQ * 32;
    constexpr int WM = BM / WMQ, WN = BN / WNQ;
    constexpr int FM = WM / 16, FN = WN / 8;
    constexpr int K  = (EPI == 1) ? CDIM : NCDIM;
    constexpr int Nn = (EPI == 0) ? 32 : ((EPI == 1) ? DFFDIM : CDIM);
    constexpr int KT = K / BK;
    constexpr int ACH = BM * BK / 8, BCH = BN * BK / 8;
    constexpr int APT = ACH / THREADS;
    constexpr int BPT = BCH / THREADS;

    const __half* __restrict__ A  = (EPI == 0) ? g_xh   : (EPI == 1) ? g_xinh : g_hidh;
    const __half* __restrict__ Bt = (EPI == 0) ? g_phit : (EPI == 1) ? g_w1t  : g_w2t;

    __shared__ alignas(16) __half sA[2][BM * BK];
    __shared__ alignas(16) __half sB[2][BN * BK];
    uint32_t sAb = (uint32_t)__cvta_generic_to_shared(&sA[0][0]);
    uint32_t sBb = (uint32_t)__cvta_generic_to_shared(&sB[0][0]);

    const int tid = threadIdx.x;
    const int mBase = blockIdx.y * BM;
    const int nBase = blockIdx.x * BN;

    auto loadTiles = [&](int stg, int kt) {
        int k0 = kt * BK;
        #pragma unroll
        for (int it = 0; it < APT; it++) {
            int ch = tid + it * THREADS;
            int row = ch >> 2, k8 = ch & 3;
            const __half* g = A + (size_t)(mBase + row) * K + k0 + k8 * 8;
            uint32_t d = sAb + 2 * (stg * BM * BK + row * BK + ((k8 ^ ((row >> 1) & 3)) << 3));
            CP_ASYNC16(d, g);
        }
        #pragma unroll
        for (int it = 0; it < BPT; it++) {
            int ch = tid + it * THREADS;
            int row = ch >> 2, k8 = ch & 3;
            const __half* g = Bt + (size_t)(nBase + row) * K + k0 + k8 * 8;
            uint32_t d = sBb + 2 * (stg * BN * BK + row * BK + ((k8 ^ ((row >> 1) & 3)) << 3));
            CP_ASYNC16(d, g);
        }
    };

    const int warp = tid >> 5, lane = tid & 31;
    const int wm = warp / WNQ, wn = warp % WNQ;

    float acc[FM][FN][4];
    #pragma unroll
    for (int i = 0; i < FM; i++)
        #pragma unroll
        for (int j = 0; j < FN; j++)
            #pragma unroll
            for (int q = 0; q < 4; q++) acc[i][j][q] = 0.f;

    const int aRow = lane & 15;
    const int aKc  = lane >> 4;
    const int bRow = lane & 7;
    const int bKc  = (lane >> 3) & 1;

    loadTiles(0, 0);
    CP_COMMIT();
    for (int kt = 0; kt < KT; kt++) {
        int cur = kt & 1;
        if (kt + 1 < KT) { loadTiles(cur ^ 1, kt + 1); CP_COMMIT(); CP_WAIT(1); }
        else             { CP_WAIT(0); }
        __syncthreads();

        #pragma unroll
        for (int ks = 0; ks < 2; ks++) {
            uint32_t a[FM][4];
            uint32_t b[FN][2];
            #pragma unroll
            for (int fm = 0; fm < FM; fm++) {
                int row = wm * WM + fm * 16 + aRow;
                int k8  = ks * 2 + aKc;
                uint32_t ad = sAb + 2 * (cur * BM * BK + row * BK + ((k8 ^ ((row >> 1) & 3)) << 3));
                asm volatile("ldmatrix.sync.aligned.m8n8.x4.shared.b16 {%0,%1,%2,%3}, [%4];\n"
                             : "=r"(a[fm][0]), "=r"(a[fm][1]), "=r"(a[fm][2]), "=r"(a[fm][3])
                             : "r"(ad));
            }
            #pragma unroll
            for (int fn = 0; fn < FN; fn++) {
                int row = wn * WN + fn * 8 + bRow;
                int k8  = ks * 2 + bKc;
                uint32_t bd = sBb + 2 * (cur * BN * BK + row * BK + ((k8 ^ ((row >> 1) & 3)) << 3));
                asm volatile("ldmatrix.sync.aligned.m8n8.x2.shared.b16 {%0,%1}, [%2];\n"
                             : "=r"(b[fn][0]), "=r"(b[fn][1])
                             : "r"(bd));
            }
            #pragma unroll
            for (int fm = 0; fm < FM; fm++)
                #pragma unroll
                for (int fn = 0; fn < FN; fn++) {
                    asm volatile(
                        "mma.sync.aligned.m16n8k16.row.col.f32.f16.f16.f32 "
                        "{%0,%1,%2,%3}, {%4,%5,%6,%7}, {%8,%9}, {%0,%1,%2,%3};\n"
                        : "+f"(acc[fm][fn][0]), "+f"(acc[fm][fn][1]),
                          "+f"(acc[fm][fn][2]), "+f"(acc[fm][fn][3])
                        : "r"(a[fm][0]), "r"(a[fm][1]), "r"(a[fm][2]), "r"(a[fm][3]),
                          "r"(b[fn][0]), "r"(b[fn][1]));
                }
        }
        __syncthreads();
    }

    // epilogue
    const int gq = lane >> 2, cq = lane & 3;
    #pragma unroll
    for (int fm = 0; fm < FM; fm++) {
        #pragma unroll
        for (int fn = 0; fn < FN; fn++) {
            int r0 = mBase + wm * WM + fm * 16 + gq;
            int c0 = nBase + wn * WN + fn * 8 + cq * 2;
            if constexpr (EPI == 0) {
                float2* o = (float2*)g_mix;
                o[((size_t)r0 * 32 + c0) >> 1]       = make_float2(acc[fm][fn][0], acc[fm][fn][1]);
                o[((size_t)(r0 + 8) * 32 + c0) >> 1] = make_float2(acc[fm][fn][2], acc[fm][fn][3]);
            } else if constexpr (EPI == 1) {
                float bz0 = bias[c0], bz1 = bias[c0 + 1];
                float v0 = gelu_exact(acc[fm][fn][0] + bz0);
                float v1 = gelu_exact(acc[fm][fn][1] + bz1);
                float v2 = gelu_exact(acc[fm][fn][2] + bz0);
                float v3 = gelu_exact(acc[fm][fn][3] + bz1);
                __half2* o = (__half2*)g_hidh;
                o[((size_t)r0 * Nn + c0) >> 1]       = __floats2half2_rn(v0, v1);
                o[((size_t)(r0 + 8) * Nn + c0) >> 1] = __floats2half2_rn(v2, v3);
            } else {
                float bz0 = bias[c0], bz1 = bias[c0 + 1];
                float2* o = (float2*)g_fout;
                o[((size_t)r0 * Nn + c0) >> 1]       = make_float2(acc[fm][fn][0] + bz0, acc[fm][fn][1] + bz1);
                o[((size_t)(r0 + 8) * Nn + c0) >> 1] = make_float2(acc[fm][fn][2] + bz0, acc[fm][fn][3] + bz1);
            }
        }
    }
}

// ---------------- kernel 3: routing (sigmoid / sinkhorn) ----------------
__global__ void routing_kernel(const float* __restrict__ b,
                               const float* __restrict__ apre,
                               const float* __restrict__ apost,
                               const float* __restrict__ ares) {
    int t = blockIdx.x * blockDim.x + threadIdx.x;
    if (t >= TOK) return;
    float invr = g_invr[t];
    float m[24];
    #pragma unroll
    for (int i = 0; i < 24; i++) m[i] = g_mix[(size_t)t * 32 + i] * invr;
    float ap = apre[0], apo = apost[0], ar = ares[0];
    #pragma unroll
    for (int n = 0; n < 4; n++) {
        float z = m[n] * ap + b[n];
        g_hpre[t * 4 + n] = 1.0f / (1.0f + expf(-z));
    }
    #pragma unroll
    for (int n = 0; n < 4; n++) {
        float z = m[4 + n] * apo + b[4 + n];
        g_hpost[t * 4 + n] = 2.0f / (1.0f + expf(-z));
    }
    float r[16];
    #pragma unroll
    for (int i = 0; i < 16; i++) r[i] = m[8 + i] * ar + b[8 + i];
    #pragma unroll
    for (int row = 0; row < 4; row++) {
        float mx = r[row * 4];
        #pragma unroll
        for (int j = 1; j < 4; j++) mx = fmaxf(mx, r[row * 4 + j]);
        #pragma unroll
        for (int j = 0; j < 4; j++) r[row * 4 + j] = expf(r[row * 4 + j] - mx);
    }
    for (int it = 0; it < 20; it++) {
        #pragma unroll
        for (int row = 0; row < 4; row++) {
            float s = r[row * 4] + r[row * 4 + 1] + r[row * 4 + 2] + r[row * 4 + 3] + 1e-6f;
            float inv = 1.0f / s;
            #pragma unroll
            for (int j = 0; j < 4; j++) r[row * 4 + j] *= inv;
        }
        #pragma unroll
        for (int col = 0; col < 4; col++) {
            float s = r[col] + r[4 + col] + r[8 + col] + r[12 + col] + 1e-6f;
            float inv = 1.0f / s;
            #pragma unroll
            for (int row = 0; row < 4; row++) r[row * 4 + col] *= inv;
        }
    }
    #pragma unroll
    for (int i = 0; i < 16; i++) g_hres[t * 16 + i] = r[i];
}

// ---------------- kernel 4: x_in = sum_n h_pre[n] * x[n,:] ----------------
__global__ void xin_kernel() {
    int idx = blockIdx.x * blockDim.x + threadIdx.x;  // over TOK*384 half2
    if (idx >= TOK * 384) return;
    int t = idx / 384, c2 = idx % 384;
    const __half2* xh2 = (const __half2*)g_xh;
    float ax = 0.f, ay = 0.f;
    #pragma unroll
    for (int n = 0; n < 4; n++) {
        float2 v = __half22float2(xh2[(size_t)t * 1536 + n * 384 + c2]);
        float h = g_hpre[t * 4 + n];
        ax += h * v.x; ay += h * v.y;
    }
    ((__half2*)g_xinh)[(size_t)t * 384 + c2] = __floats2half2_rn(ax, ay);
}

// ---------------- kernel 7: out = h_res@x + h_post * f_out ----------------
__global__ void final_kernel(float* __restrict__ out) {
    int idx = blockIdx.x * blockDim.x + threadIdx.x;  // over TOK*384 float2
    if (idx >= TOK * 384) return;
    int t = idx / 384, c2 = idx % 384;
    float2 f = ((const float2*)g_fout)[(size_t)t * 384 + c2];
    const __half2* xh2 = (const __half2*)g_xh;
    float2 xv[4];
    #pragma unroll
    for (int j = 0; j < 4; j++)
        xv[j] = __half22float2(xh2[(size_t)t * 1536 + j * 384 + c2]);
    #pragma unroll
    for (int n = 0; n < 4; n++) {
        float hp = g_hpost[t * 4 + n];
        float ox = hp * f.x, oy = hp * f.y;
        #pragma unroll
        for (int j = 0; j < 4; j++) {
            float w = g_hres[t * 16 + n * 4 + j];
            ox += w * xv[j].x; oy += w * xv[j].y;
        }
        ((float2*)out)[((size_t)t * 4 + n) * 384 + c2] = make_float2(ox, oy);
    }
}

// ---------------- launch ----------------
extern "C" void kernel_launch(void* const* d_in, const int* in_sizes, int n_in,
                              void* d_out, int out_size) {
    const float* x     = (const float*)d_in[0];
    const float* phi   = (const float*)d_in[1];
    const float* b     = (const float*)d_in[2];
    const float* apre  = (const float*)d_in[3];
    const float* apost = (const float*)d_in[4];
    const float* ares  = (const float*)d_in[5];
    const float* W1    = (const float*)d_in[6];
    const float* b1    = (const float*)d_in[7];
    const float* W2    = (const float*)d_in[8];
    const float* b2    = (const float*)d_in[9];
    float* out = (float*)d_out;

    prep_kernel<<<1024, 256>>>(W1, W2, phi);
    sumsq_convert_kernel<<<TOK / 8, 256>>>(x);
    gemm_mma<0><<<dim3(1, TOK / 128), 128>>>(nullptr);
    routing_kernel<<<TOK / 256, 256>>>(b, apre, apost, ares);
    xin_kernel<<<TOK * 384 / 256, 256>>>();
    gemm_mma<1><<<dim3(DFFDIM / 128, TOK / 128), 256>>>(b1);
    gemm_mma<2><<<dim3(CDIM / 128, TOK / 128), 256>>>(b2);
    final_kernel<<<TOK * 384 / 256, 256>>>(out);
}

// round 6
// speedup vs baseline: 1.0058x; 1.0058x over previous
#include <cuda_runtime.h>
#include <cuda_fp16.h>
#include <stdint.h>

#define TOK 16384
#define CDIM 768
#define NCDIM 3072
#define DFFDIM 3072

// ---------------- device scratch (static; no allocs allowed) ----------------
__device__ __half g_xh[(size_t)TOK * NCDIM];      // x in fp16
__device__ float  g_invr[TOK];
__device__ __half g_phit[32 * NCDIM];             // phi^T padded [32][3072]
__device__ __half g_w1t[(size_t)DFFDIM * CDIM];   // W1^T [3072][768]
__device__ __half g_w2t[(size_t)CDIM * DFFDIM];   // W2^T [768][3072]
__device__ float  g_mix[(size_t)TOK * 32];        // raw x@phi (pre-invr)
__device__ float  g_hpre[TOK * 4];
__device__ float  g_hpost[TOK * 4];
__device__ float  g_hres[TOK * 16];
__device__ __half g_xinh[(size_t)TOK * CDIM];     // pre-aggregated stream, fp16
__device__ __half g_hidh[(size_t)TOK * DFFDIM];   // gelu(x_in@W1+b1), fp16

// ---------------- kernel 0: convert + transpose weights (R2-proven) ----------------
__global__ void prep_kernel(const float* __restrict__ W1,
                            const float* __restrict__ W2,
                            const float* __restrict__ phi) {
    int i = blockIdx.x * blockDim.x + threadIdx.x;
    int stride = gridDim.x * blockDim.x;
    for (int idx = i; idx < DFFDIM * CDIM; idx += stride) {
        int n = idx / CDIM, k = idx % CDIM;
        g_w1t[idx] = __float2half(W1[(size_t)k * DFFDIM + n]);
    }
    for (int idx = i; idx < CDIM * DFFDIM; idx += stride) {
        int n = idx / DFFDIM, k = idx % DFFDIM;
        g_w2t[idx] = __float2half(W2[(size_t)k * CDIM + n]);
    }
    for (int idx = i; idx < 32 * NCDIM; idx += stride) {
        int j = idx / NCDIM, k = idx % NCDIM;
        g_phit[idx] = (j < 24) ? __float2half(phi[k * 24 + j]) : __float2half(0.0f);
    }
}

// ---------------- kernel 1: rms sumsq + fp32->fp16 convert ----------------
__global__ void sumsq_convert_kernel(const float* __restrict__ x) {
    int gw = (blockIdx.x * blockDim.x + threadIdx.x) >> 5;
    int lane = threadIdx.x & 31;
    if (gw >= TOK) return;
    const float4* row = (const float4*)(x + (size_t)gw * NCDIM);
    __half2* outrow = (__half2*)(g_xh + (size_t)gw * NCDIM);
    float ss = 0.f;
    #pragma unroll 4
    for (int i = lane; i < NCDIM / 4; i += 32) {
        float4 v = row[i];
        ss += v.x * v.x + v.y * v.y + v.z * v.z + v.w * v.w;
        outrow[2 * i]     = __floats2half2_rn(v.x, v.y);
        outrow[2 * i + 1] = __floats2half2_rn(v.z, v.w);
    }
    #pragma unroll
    for (int o = 16; o; o >>= 1) ss += __shfl_xor_sync(0xffffffffu, ss, o);
    if (lane == 0) g_invr[gw] = rsqrtf(ss / (float)NCDIM + 1e-6f);
}

// ---------------- mma.sync GEMM (fp16 in, fp32 acc) — R2-proven core ----------------
#define CP_ASYNC16(dst, src) asm volatile("cp.async.cg.shared.global [%0], [%1], 16;\n" :: "r"(dst), "l"(src))
#define CP_COMMIT() asm volatile("cp.async.commit_group;\n" ::)
#define CP_WAIT(N_) asm volatile("cp.async.wait_group %0;\n" :: "n"(N_))

__device__ __forceinline__ float gelu_exact(float v) {
    return 0.5f * v * (1.0f + erff(v * 0.70710678118654752f));
}

// EPI 0: mix = x_h @ phi_t          (M=16384, N=32,  K=3072) -> g_mix (fp32, raw)
// EPI 1: hid = gelu(xin@W1 + b1)    (M=16384, N=3072,K=768)  -> g_hidh (fp16)
// EPI 2: out = hres@x + hpost*(hid@W2 + b2)   (fused final scatter)
template <int EPI>
__global__ void __launch_bounds__((EPI == 0) ? 128 : 256, 2)
gemm_mma(const float* __restrict__ bias, float* __restrict__ out) {
    constexpr int BM = 128, BK = 32;
    constexpr int BN  = (EPI == 0) ? 32 : 128;
    constexpr int WMQ = (EPI == 0) ? 4 : 2;
    constexpr int WNQ = (EPI == 0) ? 1 : 4;
    constexpr int THREADS = WMQ * WNQ * 32;
    constexpr int WM = BM / WMQ, WN = BN / WNQ;
    constexpr int FM = WM / 16, FN = WN / 8;
    constexpr int K  = (EPI == 1) ? CDIM : NCDIM;
    constexpr int Nn = (EPI == 0) ? 32 : ((EPI == 1) ? DFFDIM : CDIM);
    constexpr int KT = K / BK;
    constexpr int ACH = BM * BK / 8, BCH = BN * BK / 8;
    constexpr int APT = ACH / THREADS;
    constexpr int BPT = BCH / THREADS;

    const __half* __restrict__ A  = (EPI == 0) ? g_xh   : (EPI == 1) ? g_xinh : g_hidh;
    const __half* __restrict__ Bt = (EPI == 0) ? g_phit : (EPI == 1) ? g_w1t  : g_w2t;

    __shared__ alignas(16) __half sA[2][BM * BK];
    __shared__ alignas(16) __half sB[2][BN * BK];
    uint32_t sAb = (uint32_t)__cvta_generic_to_shared(&sA[0][0]);
    uint32_t sBb = (uint32_t)__cvta_generic_to_shared(&sB[0][0]);

    const int tid = threadIdx.x;
    const int mBase = blockIdx.y * BM;
    const int nBase = blockIdx.x * BN;

    auto loadTiles = [&](int stg, int kt) {
        int k0 = kt * BK;
        #pragma unroll
        for (int it = 0; it < APT; it++) {
            int ch = tid + it * THREADS;
            int row = ch >> 2, k8 = ch & 3;
            const __half* g = A + (size_t)(mBase + row) * K + k0 + k8 * 8;
            uint32_t d = sAb + 2 * (stg * BM * BK + row * BK + ((k8 ^ ((row >> 1) & 3)) << 3));
            CP_ASYNC16(d, g);
        }
        #pragma unroll
        for (int it = 0; it < BPT; it++) {
            int ch = tid + it * THREADS;
            int row = ch >> 2, k8 = ch & 3;
            const __half* g = Bt + (size_t)(nBase + row) * K + k0 + k8 * 8;
            uint32_t d = sBb + 2 * (stg * BN * BK + row * BK + ((k8 ^ ((row >> 1) & 3)) << 3));
            CP_ASYNC16(d, g);
        }
    };

    const int warp = tid >> 5, lane = tid & 31;
    const int wm = warp / WNQ, wn = warp % WNQ;

    float acc[FM][FN][4];
    #pragma unroll
    for (int i = 0; i < FM; i++)
        #pragma unroll
        for (int j = 0; j < FN; j++)
            #pragma unroll
            for (int q = 0; q < 4; q++) acc[i][j][q] = 0.f;

    const int aRow = lane & 15;
    const int aKc  = lane >> 4;
    const int bRow = lane & 7;
    const int bKc  = (lane >> 3) & 1;

    loadTiles(0, 0);
    CP_COMMIT();
    for (int kt = 0; kt < KT; kt++) {
        int cur = kt & 1;
        if (kt + 1 < KT) { loadTiles(cur ^ 1, kt + 1); CP_COMMIT(); CP_WAIT(1); }
        else             { CP_WAIT(0); }
        __syncthreads();

        #pragma unroll
        for (int ks = 0; ks < 2; ks++) {
            uint32_t a[FM][4];
            uint32_t b[FN][2];
            #pragma unroll
            for (int fm = 0; fm < FM; fm++) {
                int row = wm * WM + fm * 16 + aRow;
                int k8  = ks * 2 + aKc;
                uint32_t ad = sAb + 2 * (cur * BM * BK + row * BK + ((k8 ^ ((row >> 1) & 3)) << 3));
                asm volatile("ldmatrix.sync.aligned.m8n8.x4.shared.b16 {%0,%1,%2,%3}, [%4];\n"
                             : "=r"(a[fm][0]), "=r"(a[fm][1]), "=r"(a[fm][2]), "=r"(a[fm][3])
                             : "r"(ad));
            }
            #pragma unroll
            for (int fn = 0; fn < FN; fn++) {
                int row = wn * WN + fn * 8 + bRow;
                int k8  = ks * 2 + bKc;
                uint32_t bd = sBb + 2 * (cur * BN * BK + row * BK + ((k8 ^ ((row >> 1) & 3)) << 3));
                asm volatile("ldmatrix.sync.aligned.m8n8.x2.shared.b16 {%0,%1}, [%2];\n"
                             : "=r"(b[fn][0]), "=r"(b[fn][1])
                             : "r"(bd));
            }
            #pragma unroll
            for (int fm = 0; fm < FM; fm++)
                #pragma unroll
                for (int fn = 0; fn < FN; fn++) {
                    asm volatile(
                        "mma.sync.aligned.m16n8k16.row.col.f32.f16.f16.f32 "
                        "{%0,%1,%2,%3}, {%4,%5,%6,%7}, {%8,%9}, {%0,%1,%2,%3};\n"
                        : "+f"(acc[fm][fn][0]), "+f"(acc[fm][fn][1]),
                          "+f"(acc[fm][fn][2]), "+f"(acc[fm][fn][3])
                        : "r"(a[fm][0]), "r"(a[fm][1]), "r"(a[fm][2]), "r"(a[fm][3]),
                          "r"(b[fn][0]), "r"(b[fn][1]));
                }
        }
        __syncthreads();
    }

    // epilogue
    const int gq = lane >> 2, cq = lane & 3;
    if constexpr (EPI == 0) {
        #pragma unroll
        for (int fm = 0; fm < FM; fm++)
            #pragma unroll
            for (int fn = 0; fn < FN; fn++) {
                int r0 = mBase + wm * WM + fm * 16 + gq;
                int c0 = nBase + wn * WN + fn * 8 + cq * 2;
                float2* o = (float2*)g_mix;
                o[((size_t)r0 * 32 + c0) >> 1]       = make_float2(acc[fm][fn][0], acc[fm][fn][1]);
                o[((size_t)(r0 + 8) * 32 + c0) >> 1] = make_float2(acc[fm][fn][2], acc[fm][fn][3]);
            }
    } else if constexpr (EPI == 1) {
        #pragma unroll
        for (int fm = 0; fm < FM; fm++)
            #pragma unroll
            for (int fn = 0; fn < FN; fn++) {
                int r0 = mBase + wm * WM + fm * 16 + gq;
                int c0 = nBase + wn * WN + fn * 8 + cq * 2;
                float bz0 = bias[c0], bz1 = bias[c0 + 1];
                float v0 = gelu_exact(acc[fm][fn][0] + bz0);
                float v1 = gelu_exact(acc[fm][fn][1] + bz1);
                float v2 = gelu_exact(acc[fm][fn][2] + bz0);
                float v3 = gelu_exact(acc[fm][fn][3] + bz1);
                __half2* o = (__half2*)g_hidh;
                o[((size_t)r0 * Nn + c0) >> 1]       = __floats2half2_rn(v0, v1);
                o[((size_t)(r0 + 8) * Nn + c0) >> 1] = __floats2half2_rn(v2, v3);
            }
    } else {
        // fused: out[t][n][c] = sum_j hres[t][n][j]*x[t][j][c] + hpost[t][n]*(acc + b2[c])
        #pragma unroll
        for (int fm = 0; fm < FM; fm++) {
            int r0 = mBase + wm * WM + fm * 16 + gq;
            int r1 = r0 + 8;
            float hp0[4], hp1[4], hr0[16], hr1[16];
            #pragma unroll
            for (int n = 0; n < 4; n++) { hp0[n] = g_hpost[r0 * 4 + n]; hp1[n] = g_hpost[r1 * 4 + n]; }
            #pragma unroll
            for (int i = 0; i < 16; i++) { hr0[i] = g_hres[r0 * 16 + i]; hr1[i] = g_hres[r1 * 16 + i]; }
            #pragma unroll
            for (int fn = 0; fn < FN; fn++) {
                int c0 = nBase + wn * WN + fn * 8 + cq * 2;
                float bz0 = bias[c0], bz1 = bias[c0 + 1];
                float f0x = acc[fm][fn][0] + bz0, f0y = acc[fm][fn][1] + bz1;
                float f1x = acc[fm][fn][2] + bz0, f1y = acc[fm][fn][3] + bz1;
                float2 x0[4], x1[4];
                #pragma unroll
                for (int j = 0; j < 4; j++) {
                    x0[j] = __half22float2(*(const __half2*)(g_xh + (size_t)r0 * NCDIM + j * CDIM + c0));
                    x1[j] = __half22float2(*(const __half2*)(g_xh + (size_t)r1 * NCDIM + j * CDIM + c0));
                }
                #pragma unroll
                for (int n = 0; n < 4; n++) {
                    float ox = hp0[n] * f0x, oy = hp0[n] * f0y;
                    #pragma unroll
                    for (int j = 0; j < 4; j++) {
                        ox += hr0[n * 4 + j] * x0[j].x;
                        oy += hr0[n * 4 + j] * x0[j].y;
                    }
                    *(float2*)(out + ((size_t)r0 * 4 + n) * CDIM + c0) = make_float2(ox, oy);
                }
                #pragma unroll
                for (int n = 0; n < 4; n++) {
                    float ox = hp1[n] * f1x, oy = hp1[n] * f1y;
                    #pragma unroll
                    for (int j = 0; j < 4; j++) {
                        ox += hr1[n * 4 + j] * x1[j].x;
                        oy += hr1[n * 4 + j] * x1[j].y;
                    }
                    *(float2*)(out + ((size_t)r1 * 4 + n) * CDIM + c0) = make_float2(ox, oy);
                }
            }
        }
    }
}

// ---------------- kernel 3: routing (sigmoid / sinkhorn) ----------------
__global__ void routing_kernel(const float* __restrict__ b,
                               const float* __restrict__ apre,
                               const float* __restrict__ apost,
                               const float* __restrict__ ares) {
    int t = blockIdx.x * blockDim.x + threadIdx.x;
    if (t >= TOK) return;
    float invr = g_invr[t];
    float m[24];
    #pragma unroll
    for (int i = 0; i < 24; i++) m[i] = g_mix[(size_t)t * 32 + i] * invr;
    float ap = apre[0], apo = apost[0], ar = ares[0];
    #pragma unroll
    for (int n = 0; n < 4; n++)
        g_hpre[t * 4 + n] = 1.0f / (1.0f + expf(-(m[n] * ap + b[n])));
    #pragma unroll
    for (int n = 0; n < 4; n++)
        g_hpost[t * 4 + n] = 2.0f / (1.0f + expf(-(m[4 + n] * apo + b[4 + n])));
    float r[16];
    #pragma unroll
    for (int i = 0; i < 16; i++) r[i] = m[8 + i] * ar + b[8 + i];
    #pragma unroll
    for (int row = 0; row < 4; row++) {
        float mx = r[row * 4];
        #pragma unroll
        for (int j = 1; j < 4; j++) mx = fmaxf(mx, r[row * 4 + j]);
        #pragma unroll
        for (int j = 0; j < 4; j++) r[row * 4 + j] = expf(r[row * 4 + j] - mx);
    }
    for (int it = 0; it < 20; it++) {
        #pragma unroll
        for (int row = 0; row < 4; row++) {
            float inv = 1.0f / (r[row * 4] + r[row * 4 + 1] + r[row * 4 + 2] + r[row * 4 + 3] + 1e-6f);
            #pragma unroll
            for (int j = 0; j < 4; j++) r[row * 4 + j] *= inv;
        }
        #pragma unroll
        for (int col = 0; col < 4; col++) {
            float inv = 1.0f / (r[col] + r[4 + col] + r[8 + col] + r[12 + col] + 1e-6f);
            #pragma unroll
            for (int row = 0; row < 4; row++) r[row * 4 + col] *= inv;
        }
    }
    #pragma unroll
    for (int i = 0; i < 16; i++) g_hres[t * 16 + i] = r[i];
}

// ---------------- kernel 4: x_in = sum_n h_pre[n] * x[n,:] ----------------
__global__ void xin_kernel() {
    int idx = blockIdx.x * blockDim.x + threadIdx.x;
    if (idx >= TOK * 384) return;
    int t = idx / 384, c2 = idx % 384;
    const __half2* xh2 = (const __half2*)g_xh;
    float ax = 0.f, ay = 0.f;
    #pragma unroll
    for (int n = 0; n < 4; n++) {
        float2 v = __half22float2(xh2[(size_t)t * 1536 + n * 384 + c2]);
        float h = g_hpre[t * 4 + n];
        ax += h * v.x; ay += h * v.y;
    }
    ((__half2*)g_xinh)[(size_t)t * 384 + c2] = __floats2half2_rn(ax, ay);
}

// ---------------- launch ----------------
extern "C" void kernel_launch(void* const* d_in, const int* in_sizes, int n_in,
                              void* d_out, int out_size) {
    const float* x     = (const float*)d_in[0];
    const float* phi   = (const float*)d_in[1];
    const float* b     = (const float*)d_in[2];
    const float* apre  = (const float*)d_in[3];
    const float* apost = (const float*)d_in[4];
    const float* ares  = (const float*)d_in[5];
    const float* W1    = (const float*)d_in[6];
    const float* b1    = (const float*)d_in[7];
    const float* W2    = (const float*)d_in[8];
    const float* b2    = (const float*)d_in[9];
    float* out = (float*)d_out;

    prep_kernel<<<1024, 256>>>(W1, W2, phi);
    sumsq_convert_kernel<<<TOK / 8, 256>>>(x);
    gemm_mma<0><<<dim3(1, TOK / 128), 128>>>(nullptr, nullptr);
    routing_kernel<<<TOK / 256, 256>>>(b, apre, apost, ares);
    xin_kernel<<<TOK * 384 / 256, 256>>>();
    gemm_mma<1><<<dim3(DFFDIM / 128, TOK / 128), 256>>>(b1, nullptr);
    gemm_mma<2><<<dim3(CDIM / 128, TOK / 128), 256>>>(b2, out);
}

// round 8
// speedup vs baseline: 1.0489x; 1.0429x over previous
#include <cuda_runtime.h>
#include <cuda_fp16.h>
#include <stdint.h>

#define TOK 16384
#define CDIM 768
#define NCDIM 3072
#define DFFDIM 3072

// ---------------- device scratch (static; no allocs allowed) ----------------
__device__ __half g_xh[(size_t)TOK * NCDIM];      // x in fp16
__device__ float  g_invr[TOK];
__device__ __half g_phit[32 * NCDIM];             // phi^T padded [32][3072]
__device__ __half g_w1t[(size_t)DFFDIM * CDIM];   // W1^T [3072][768]
__device__ __half g_w2t[(size_t)CDIM * DFFDIM];   // W2^T [768][3072]
__device__ float  g_mix[(size_t)TOK * 32];        // raw x@phi (pre-invr)
__device__ float  g_hpre[TOK * 4];
__device__ float  g_hpost[TOK * 4];
__device__ float  g_hres[TOK * 16];
__device__ __half g_xinh[(size_t)TOK * CDIM];     // pre-aggregated stream, fp16
__device__ __half g_hidh[(size_t)TOK * DFFDIM];   // gelu(x_in@W1+b1), fp16

// ---------------- kernel 0: convert + transpose weights (R2/R6-proven) ----------------
__global__ void prep_kernel(const float* __restrict__ W1,
                            const float* __restrict__ W2,
                            const float* __restrict__ phi) {
    int i = blockIdx.x * blockDim.x + threadIdx.x;
    int stride = gridDim.x * blockDim.x;
    for (int idx = i; idx < DFFDIM * CDIM; idx += stride) {
        int n = idx / CDIM, k = idx % CDIM;
        g_w1t[idx] = __float2half(W1[(size_t)k * DFFDIM + n]);
    }
    for (int idx = i; idx < CDIM * DFFDIM; idx += stride) {
        int n = idx / DFFDIM, k = idx % DFFDIM;
        g_w2t[idx] = __float2half(W2[(size_t)k * CDIM + n]);
    }
    for (int idx = i; idx < 32 * NCDIM; idx += stride) {
        int j = idx / NCDIM, k = idx % NCDIM;
        g_phit[idx] = (j < 24) ? __float2half(phi[k * 24 + j]) : __float2half(0.0f);
    }
}

// ---------------- kernel 1: rms sumsq + fp32->fp16 convert ----------------
__global__ void sumsq_convert_kernel(const float* __restrict__ x) {
    int gw = (blockIdx.x * blockDim.x + threadIdx.x) >> 5;
    int lane = threadIdx.x & 31;
    if (gw >= TOK) return;
    const float4* row = (const float4*)(x + (size_t)gw * NCDIM);
    __half2* outrow = (__half2*)(g_xh + (size_t)gw * NCDIM);
    float ss = 0.f;
    #pragma unroll 4
    for (int i = lane; i < NCDIM / 4; i += 32) {
        float4 v = row[i];
        ss += v.x * v.x + v.y * v.y + v.z * v.z + v.w * v.w;
        outrow[2 * i]     = __floats2half2_rn(v.x, v.y);
        outrow[2 * i + 1] = __floats2half2_rn(v.z, v.w);
    }
    #pragma unroll
    for (int o = 16; o; o >>= 1) ss += __shfl_xor_sync(0xffffffffu, ss, o);
    if (lane == 0) g_invr[gw] = rsqrtf(ss / (float)NCDIM + 1e-6f);
}

// ---------------- cp.async helpers ----------------
#define CP_ASYNC16(dst, src) asm volatile("cp.async.cg.shared.global [%0], [%1], 16;\n" :: "r"(dst), "l"(src))
#define CP_COMMIT() asm volatile("cp.async.commit_group;\n" ::)
#define CP_WAIT(N_) asm volatile("cp.async.wait_group %0;\n" :: "n"(N_))

__device__ __forceinline__ float gelu_exact(float v) {
    return 0.5f * v * (1.0f + erff(v * 0.70710678118654752f));
}

// ---------------- R6-proven GEMM template (used here only for EPI 0: mix) ----------------
template <int EPI>
__global__ void __launch_bounds__((EPI == 0) ? 128 : 256, 2)
gemm_mma(const float* __restrict__ bias, float* __restrict__ out) {
    constexpr int BM = 128, BK = 32;
    constexpr int BN  = (EPI == 0) ? 32 : 128;
    constexpr int WMQ = (EPI == 0) ? 4 : 2;
    constexpr int WNQ = (EPI == 0) ? 1 : 4;
    constexpr int THREADS = WMQ * WNQ * 32;
    constexpr int WM = BM / WMQ, WN = BN / WNQ;
    constexpr int FM = WM / 16, FN = WN / 8;
    constexpr int K  = (EPI == 1) ? CDIM : NCDIM;
    constexpr int KT = K / BK;
    constexpr int ACH = BM * BK / 8, BCH = BN * BK / 8;
    constexpr int APT = ACH / THREADS;
    constexpr int BPT = BCH / THREADS;

    const __half* __restrict__ A  = (EPI == 0) ? g_xh   : (EPI == 1) ? g_xinh : g_hidh;
    const __half* __restrict__ Bt = (EPI == 0) ? g_phit : (EPI == 1) ? g_w1t  : g_w2t;

    __shared__ alignas(16) __half sA[2][BM * BK];
    __shared__ alignas(16) __half sB[2][BN * BK];
    uint32_t sAb = (uint32_t)__cvta_generic_to_shared(&sA[0][0]);
    uint32_t sBb = (uint32_t)__cvta_generic_to_shared(&sB[0][0]);

    const int tid = threadIdx.x;
    const int mBase = blockIdx.y * BM;
    const int nBase = blockIdx.x * BN;

    auto loadTiles = [&](int stg, int kt) {
        int k0 = kt * BK;
        #pragma unroll
        for (int it = 0; it < APT; it++) {
            int ch = tid + it * THREADS;
            int row = ch >> 2, k8 = ch & 3;
            const __half* g = A + (size_t)(mBase + row) * K + k0 + k8 * 8;
            uint32_t d = sAb + 2 * (stg * BM * BK + row * BK + ((k8 ^ ((row >> 1) & 3)) << 3));
            CP_ASYNC16(d, g);
        }
        #pragma unroll
        for (int it = 0; it < BPT; it++) {
            int ch = tid + it * THREADS;
            int row = ch >> 2, k8 = ch & 3;
            const __half* g = Bt + (size_t)(nBase + row) * K + k0 + k8 * 8;
            uint32_t d = sBb + 2 * (stg * BN * BK + row * BK + ((k8 ^ ((row >> 1) & 3)) << 3));
            CP_ASYNC16(d, g);
        }
    };

    const int warp = tid >> 5, lane = tid & 31;
    const int wm = warp / WNQ, wn = warp % WNQ;

    float acc[FM][FN][4];
    #pragma unroll
    for (int i = 0; i < FM; i++)
        #pragma unroll
        for (int j = 0; j < FN; j++)
            #pragma unroll
            for (int q = 0; q < 4; q++) acc[i][j][q] = 0.f;

    const int aRow = lane & 15;
    const int aKc  = lane >> 4;
    const int bRow = lane & 7;
    const int bKc  = (lane >> 3) & 1;

    loadTiles(0, 0);
    CP_COMMIT();
    for (int kt = 0; kt < KT; kt++) {
        int cur = kt & 1;
        if (kt + 1 < KT) { loadTiles(cur ^ 1, kt + 1); CP_COMMIT(); CP_WAIT(1); }
        else             { CP_WAIT(0); }
        __syncthreads();

        #pragma unroll
        for (int ks = 0; ks < 2; ks++) {
            uint32_t a[FM][4];
            uint32_t b[FN][2];
            #pragma unroll
            for (int fm = 0; fm < FM; fm++) {
                int row = wm * WM + fm * 16 + aRow;
                int k8  = ks * 2 + aKc;
                uint32_t ad = sAb + 2 * (cur * BM * BK + row * BK + ((k8 ^ ((row >> 1) & 3)) << 3));
                asm volatile("ldmatrix.sync.aligned.m8n8.x4.shared.b16 {%0,%1,%2,%3}, [%4];\n"
                             : "=r"(a[fm][0]), "=r"(a[fm][1]), "=r"(a[fm][2]), "=r"(a[fm][3])
                             : "r"(ad));
            }
            #pragma unroll
            for (int fn = 0; fn < FN; fn++) {
                int row = wn * WN + fn * 8 + bRow;
                int k8  = ks * 2 + bKc;
                uint32_t bd = sBb + 2 * (cur * BN * BK + row * BK + ((k8 ^ ((row >> 1) & 3)) << 3));
                asm volatile("ldmatrix.sync.aligned.m8n8.x2.shared.b16 {%0,%1}, [%2];\n"
                             : "=r"(b[fn][0]), "=r"(b[fn][1])
                             : "r"(bd));
            }
            #pragma unroll
            for (int fm = 0; fm < FM; fm++)
                #pragma unroll
                for (int fn = 0; fn < FN; fn++) {
                    asm volatile(
                        "mma.sync.aligned.m16n8k16.row.col.f32.f16.f16.f32 "
                        "{%0,%1,%2,%3}, {%4,%5,%6,%7}, {%8,%9}, {%0,%1,%2,%3};\n"
                        : "+f"(acc[fm][fn][0]), "+f"(acc[fm][fn][1]),
                          "+f"(acc[fm][fn][2]), "+f"(acc[fm][fn][3])
                        : "r"(a[fm][0]), "r"(a[fm][1]), "r"(a[fm][2]), "r"(a[fm][3]),
                          "r"(b[fn][0]), "r"(b[fn][1]));
                }
        }
        __syncthreads();
    }

    // epilogue (only EPI 0 is launched)
    const int gq = lane >> 2, cq = lane & 3;
    if constexpr (EPI == 0) {
        #pragma unroll
        for (int fm = 0; fm < FM; fm++)
            #pragma unroll
            for (int fn = 0; fn < FN; fn++) {
                int r0 = mBase + wm * WM + fm * 16 + gq;
                int c0 = nBase + wn * WN + fn * 8 + cq * 2;
                float2* o = (float2*)g_mix;
                o[((size_t)r0 * 32 + c0) >> 1]       = make_float2(acc[fm][fn][0], acc[fm][fn][1]);
                o[((size_t)(r0 + 8) * 32 + c0) >> 1] = make_float2(acc[fm][fn][2], acc[fm][fn][3]);
            }
    }
}

// ================= big GEMM: BM=128, BN=128, BK=64, 3-stage cp.async =================
// Same warp layout / fragment math / epilogues as R6-proven; only K-depth (BK 32->64,
// SW128 row swizzle) and stage count (2->3) change. Weights come from proven prep_kernel.
// EPI 1: hid = gelu(xin@W1 + b1) -> g_hidh (fp16).           A=g_xinh, K=768
// EPI 2: out = hres@x + hpost*(hid@W2 + b2) (fused scatter). A=g_hidh, K=3072
#define HP_STAGES 3
#define HP_STG_BYTES (256 * 64 * 2)   // A(128x64) + B(128x64) fp16 = 32768 B per stage

template <int KDIM, int EPI>
__global__ void __launch_bounds__(256, 2)
gemm_hp(const float* __restrict__ bias, float* __restrict__ out) {
    constexpr int BM = 128, BN = 128, BK = 64;
    constexpr int KT = KDIM / BK;

    const __half* __restrict__ A  = (EPI == 1) ? g_xinh : g_hidh;
    const __half* __restrict__ Bt = (EPI == 1) ? g_w1t  : g_w2t;

    extern __shared__ char smem_raw[];
    uint32_t sAb = (uint32_t)__cvta_generic_to_shared(smem_raw);

    const int tid = threadIdx.x, warp = tid >> 5, lane = tid & 31;
    const int mBase = blockIdx.y * BM;
    const int nBase = blockIdx.x * BN;
    const int wm = warp >> 2, wn = warp & 3;     // 2x4 warps, each 64x32 (as R6)

    // rows are 128B (8 chunks of 16B); SW128 swizzle: chunk ^= (row & 7)
    auto loadTiles = [&](int stg, int kt) {
        int k0 = kt * BK;
        uint32_t sb = sAb + stg * HP_STG_BYTES;
        #pragma unroll
        for (int it = 0; it < 4; it++) {          // A: 128 rows x 8 chunks = 1024
            int ch = tid + it * 256;
            int row = ch >> 3, c = ch & 7;
            const __half* g = A + (size_t)(mBase + row) * KDIM + k0 + c * 8;
            CP_ASYNC16(sb + row * 128 + ((c ^ (row & 7)) << 4), g);
        }
        #pragma unroll
        for (int it = 0; it < 4; it++) {          // B: 128 rows x 8 chunks = 1024
            int ch = tid + it * 256;
            int row = ch >> 3, c = ch & 7;
            const __half* g = Bt + (size_t)(nBase + row) * KDIM + k0 + c * 8;
            CP_ASYNC16(sb + 16384 + row * 128 + ((c ^ (row & 7)) << 4), g);
        }
    };

    const int aRow = lane & 15, aKc = lane >> 4;
    const int bRow = lane & 7,  bKc = (lane >> 3) & 1;

    float acc[4][4][4];
    #pragma unroll
    for (int i = 0; i < 4; i++)
        #pragma unroll
        for (int j = 0; j < 4; j++)
            #pragma unroll
            for (int q = 0; q < 4; q++) acc[i][j][q] = 0.f;

    loadTiles(0, 0); CP_COMMIT();
    loadTiles(1, 1); CP_COMMIT();

    for (int kt = 0; kt < KT; kt++) {
        int cur = kt % 3;
        // group g carries k-tile g; wait_group 2 at iter kt => groups <= kt complete =>
        // stage cur is ready. Stage being overwritten (kt+2)%3 == (kt-1)%3 is protected
        // by the trailing __syncthreads() of iteration kt-1.
        if (kt + 2 < KT) { loadTiles((kt + 2) % 3, kt + 2); CP_COMMIT(); CP_WAIT(2); }
        else             { CP_WAIT(0); }
        __syncthreads();

        uint32_t sb = sAb + cur * HP_STG_BYTES;
        #pragma unroll
        for (int ks = 0; ks < 4; ks++) {
            uint32_t a[4][4], b[4][2];
            #pragma unroll
            for (int fm = 0; fm < 4; fm++) {
                int row = wm * 64 + fm * 16 + aRow;
                int c = ks * 2 + aKc;
                uint32_t ad = sb + row * 128 + ((c ^ (row & 7)) << 4);
                asm volatile("ldmatrix.sync.aligned.m8n8.x4.shared.b16 {%0,%1,%2,%3}, [%4];\n"
                             : "=r"(a[fm][0]), "=r"(a[fm][1]), "=r"(a[fm][2]), "=r"(a[fm][3])
                             : "r"(ad));
            }
            #pragma unroll
            for (int fn = 0; fn < 4; fn++) {
                int row = wn * 32 + fn * 8 + bRow;
                int c = ks * 2 + bKc;
                uint32_t bd = sb + 16384 + row * 128 + ((c ^ (row & 7)) << 4);
                asm volatile("ldmatrix.sync.aligned.m8n8.x2.shared.b16 {%0,%1}, [%2];\n"
                             : "=r"(b[fn][0]), "=r"(b[fn][1])
                             : "r"(bd));
            }
            #pragma unroll
            for (int fm = 0; fm < 4; fm++)
                #pragma unroll
                for (int fn = 0; fn < 4; fn++)
                    asm volatile(
                        "mma.sync.aligned.m16n8k16.row.col.f32.f16.f16.f32 "
                        "{%0,%1,%2,%3}, {%4,%5,%6,%7}, {%8,%9}, {%0,%1,%2,%3};\n"
                        : "+f"(acc[fm][fn][0]), "+f"(acc[fm][fn][1]),
                          "+f"(acc[fm][fn][2]), "+f"(acc[fm][fn][3])
                        : "r"(a[fm][0]), "r"(a[fm][1]), "r"(a[fm][2]), "r"(a[fm][3]),
                          "r"(b[fn][0]), "r"(b[fn][1]));
        }
        __syncthreads();
    }

    // ---------------- epilogues (verbatim from R6-proven) ----------------
    const int gq = lane >> 2, cq = lane & 3;
    if constexpr (EPI == 1) {
        #pragma unroll
        for (int fm = 0; fm < 4; fm++)
            #pragma unroll
            for (int fn = 0; fn < 4; fn++) {
                int r0 = mBase + wm * 64 + fm * 16 + gq;
                int c0 = nBase + wn * 32 + fn * 8 + cq * 2;
                float bz0 = bias[c0], bz1 = bias[c0 + 1];
                float v0 = gelu_exact(acc[fm][fn][0] + bz0);
                float v1 = gelu_exact(acc[fm][fn][1] + bz1);
                float v2 = gelu_exact(acc[fm][fn][2] + bz0);
                float v3 = gelu_exact(acc[fm][fn][3] + bz1);
                __half2* o = (__half2*)g_hidh;
                o[((size_t)r0 * DFFDIM + c0) >> 1]       = __floats2half2_rn(v0, v1);
                o[((size_t)(r0 + 8) * DFFDIM + c0) >> 1] = __floats2half2_rn(v2, v3);
            }
    } else {
        #pragma unroll
        for (int fm = 0; fm < 4; fm++) {
            int r0 = mBase + wm * 64 + fm * 16 + gq;
            int r1 = r0 + 8;
            float hp0[4], hp1[4], hr0[16], hr1[16];
            #pragma unroll
            for (int n = 0; n < 4; n++) { hp0[n] = g_hpost[r0 * 4 + n]; hp1[n] = g_hpost[r1 * 4 + n]; }
            #pragma unroll
            for (int i = 0; i < 16; i++) { hr0[i] = g_hres[r0 * 16 + i]; hr1[i] = g_hres[r1 * 16 + i]; }
            #pragma unroll
            for (int fn = 0; fn < 4; fn++) {
                int c0 = nBase + wn * 32 + fn * 8 + cq * 2;
                float bz0 = bias[c0], bz1 = bias[c0 + 1];
                float f0x = acc[fm][fn][0] + bz0, f0y = acc[fm][fn][1] + bz1;
                float f1x = acc[fm][fn][2] + bz0, f1y = acc[fm][fn][3] + bz1;
                float2 x0[4], x1[4];
                #pragma unroll
                for (int j = 0; j < 4; j++) {
                    x0[j] = __half22float2(*(const __half2*)(g_xh + (size_t)r0 * NCDIM + j * CDIM + c0));
                    x1[j] = __half22float2(*(const __half2*)(g_xh + (size_t)r1 * NCDIM + j * CDIM + c0));
                }
                #pragma unroll
                for (int n = 0; n < 4; n++) {
                    float ox = hp0[n] * f0x, oy = hp0[n] * f0y;
                    #pragma unroll
                    for (int j = 0; j < 4; j++) {
                        ox += hr0[n * 4 + j] * x0[j].x;
                        oy += hr0[n * 4 + j] * x0[j].y;
                    }
                    *(float2*)(out + ((size_t)r0 * 4 + n) * CDIM + c0) = make_float2(ox, oy);
                }
                #pragma unroll
                for (int n = 0; n < 4; n++) {
                    float ox = hp1[n] * f1x, oy = hp1[n] * f1y;
                    #pragma unroll
                    for (int j = 0; j < 4; j++) {
                        ox += hr1[n * 4 + j] * x1[j].x;
                        oy += hr1[n * 4 + j] * x1[j].y;
                    }
                    *(float2*)(out + ((size_t)r1 * 4 + n) * CDIM + c0) = make_float2(ox, oy);
                }
            }
        }
    }
}

// ---------------- kernel 3: routing (sigmoid / sinkhorn) ----------------
__global__ void routing_kernel(const float* __restrict__ b,
                               const float* __restrict__ apre,
                               const float* __restrict__ apost,
                               const float* __restrict__ ares) {
    int t = blockIdx.x * blockDim.x + threadIdx.x;
    if (t >= TOK) return;
    float invr = g_invr[t];
    float m[24];
    #pragma unroll
    for (int i = 0; i < 24; i++) m[i] = g_mix[(size_t)t * 32 + i] * invr;
    float ap = apre[0], apo = apost[0], ar = ares[0];
    #pragma unroll
    for (int n = 0; n < 4; n++)
        g_hpre[t * 4 + n] = 1.0f / (1.0f + expf(-(m[n] * ap + b[n])));
    #pragma unroll
    for (int n = 0; n < 4; n++)
        g_hpost[t * 4 + n] = 2.0f / (1.0f + expf(-(m[4 + n] * apo + b[4 + n])));
    float r[16];
    #pragma unroll
    for (int i = 0; i < 16; i++) r[i] = m[8 + i] * ar + b[8 + i];
    #pragma unroll
    for (int row = 0; row < 4; row++) {
        float mx = r[row * 4];
        #pragma unroll
        for (int j = 1; j < 4; j++) mx = fmaxf(mx, r[row * 4 + j]);
        #pragma unroll
        for (int j = 0; j < 4; j++) r[row * 4 + j] = expf(r[row * 4 + j] - mx);
    }
    for (int it = 0; it < 20; it++) {
        #pragma unroll
        for (int row = 0; row < 4; row++) {
            float inv = 1.0f / (r[row * 4] + r[row * 4 + 1] + r[row * 4 + 2] + r[row * 4 + 3] + 1e-6f);
            #pragma unroll
            for (int j = 0; j < 4; j++) r[row * 4 + j] *= inv;
        }
        #pragma unroll
        for (int col = 0; col < 4; col++) {
            float inv = 1.0f / (r[col] + r[4 + col] + r[8 + col] + r[12 + col] + 1e-6f);
            #pragma unroll
            for (int row = 0; row < 4; row++) r[row * 4 + col] *= inv;
        }
    }
    #pragma unroll
    for (int i = 0; i < 16; i++) g_hres[t * 16 + i] = r[i];
}

// ---------------- kernel 4: x_in = sum_n h_pre[n] * x[n,:] ----------------
__global__ void xin_kernel() {
    int idx = blockIdx.x * blockDim.x + threadIdx.x;
    if (idx >= TOK * 384) return;
    int t = idx / 384, c2 = idx % 384;
    const __half2* xh2 = (const __half2*)g_xh;
    float ax = 0.f, ay = 0.f;
    #pragma unroll
    for (int n = 0; n < 4; n++) {
        float2 v = __half22float2(xh2[(size_t)t * 1536 + n * 384 + c2]);
        float h = g_hpre[t * 4 + n];
        ax += h * v.x; ay += h * v.y;
    }
    ((__half2*)g_xinh)[(size_t)t * 384 + c2] = __floats2half2_rn(ax, ay);
}

// ---------------- launch ----------------
extern "C" void kernel_launch(void* const* d_in, const int* in_sizes, int n_in,
                              void* d_out, int out_size) {
    const float* x     = (const float*)d_in[0];
    const float* phi   = (const float*)d_in[1];
    const float* b     = (const float*)d_in[2];
    const float* apre  = (const float*)d_in[3];
    const float* apost = (const float*)d_in[4];
    const float* ares  = (const float*)d_in[5];
    const float* W1    = (const float*)d_in[6];
    const float* b1    = (const float*)d_in[7];
    const float* W2    = (const float*)d_in[8];
    const float* b2    = (const float*)d_in[9];
    float* out = (float*)d_out;

    const int dyn_smem = HP_STAGES * HP_STG_BYTES;   // 96 KB
    cudaFuncSetAttribute(gemm_hp<CDIM, 1>,  cudaFuncAttributeMaxDynamicSharedMemorySize, dyn_smem);
    cudaFuncSetAttribute(gemm_hp<NCDIM, 2>, cudaFuncAttributeMaxDynamicSharedMemorySize, dyn_smem);

    prep_kernel<<<1024, 256>>>(W1, W2, phi);
    sumsq_convert_kernel<<<TOK / 8, 256>>>(x);
    gemm_mma<0><<<dim3(1, TOK / 128), 128>>>(nullptr, nullptr);
    routing_kernel<<<TOK / 256, 256>>>(b, apre, apost, ares);
    xin_kernel<<<TOK * 384 / 256, 256>>>();
    gemm_hp<CDIM, 1><<<dim3(DFFDIM / 128, TOK / 128), 256, dyn_smem>>>(b1, nullptr);
    gemm_hp<NCDIM, 2><<<dim3(CDIM / 128, TOK / 128), 256, dyn_smem>>>(b2, out);
}

// round 9
// speedup vs baseline: 1.0844x; 1.0339x over previous
#include <cuda_runtime.h>
#include <cuda_fp16.h>
#include <stdint.h>

#define TOK 16384
#define CDIM 768
#define NCDIM 3072
#define DFFDIM 3072

// ---------------- device scratch (static; no allocs allowed) ----------------
__device__ __half g_xh[(size_t)TOK * NCDIM];      // x in fp16
__device__ float  g_invr[TOK];
__device__ __half g_phit[32 * NCDIM];             // phi^T padded [32][3072]
__device__ __half g_w1h[(size_t)CDIM * DFFDIM];   // W1 fp16, native [768][3072]
__device__ __half g_w2h[(size_t)DFFDIM * CDIM];   // W2 fp16, native [3072][768]
__device__ float  g_mix[(size_t)TOK * 32];        // raw x@phi (pre-invr)
__device__ float  g_hpre[TOK * 4];
__device__ float  g_hpost[TOK * 4];
__device__ float  g_hres[TOK * 16];
__device__ __half g_xinh[(size_t)TOK * CDIM];     // pre-aggregated stream, fp16
__device__ __half g_hidh[(size_t)TOK * DFFDIM];   // gelu(x_in@W1+b1), fp16

// ---------------- weight convert (1:1, fully coalesced) + phi pad ----------------
__global__ void convert_w_kernel(const float* __restrict__ W1,
                                 const float* __restrict__ W2,
                                 const float* __restrict__ phi) {
    int i = blockIdx.x * blockDim.x + threadIdx.x;
    int stride = gridDim.x * blockDim.x;
    const int WELEM4 = (CDIM * DFFDIM) / 4;       // same count both weights
    for (int idx = i; idx < WELEM4; idx += stride) {
        float4 v = ((const float4*)W1)[idx];
        ((__half2*)g_w1h)[2 * idx]     = __floats2half2_rn(v.x, v.y);
        ((__half2*)g_w1h)[2 * idx + 1] = __floats2half2_rn(v.z, v.w);
        float4 w = ((const float4*)W2)[idx];
        ((__half2*)g_w2h)[2 * idx]     = __floats2half2_rn(w.x, w.y);
        ((__half2*)g_w2h)[2 * idx + 1] = __floats2half2_rn(w.z, w.w);
    }
    for (int idx = i; idx < 32 * NCDIM; idx += stride) {
        int j = idx / NCDIM, k = idx % NCDIM;
        g_phit[idx] = (j < 24) ? __float2half(phi[k * 24 + j]) : __float2half(0.0f);
    }
}

// ---------------- rms sumsq + fp32->fp16 convert ----------------
__global__ void sumsq_convert_kernel(const float* __restrict__ x) {
    int gw = (blockIdx.x * blockDim.x + threadIdx.x) >> 5;
    int lane = threadIdx.x & 31;
    if (gw >= TOK) return;
    const float4* row = (const float4*)(x + (size_t)gw * NCDIM);
    __half2* outrow = (__half2*)(g_xh + (size_t)gw * NCDIM);
    float ss = 0.f;
    #pragma unroll 4
    for (int i = lane; i < NCDIM / 4; i += 32) {
        float4 v = row[i];
        ss += v.x * v.x + v.y * v.y + v.z * v.z + v.w * v.w;
        outrow[2 * i]     = __floats2half2_rn(v.x, v.y);
        outrow[2 * i + 1] = __floats2half2_rn(v.z, v.w);
    }
    #pragma unroll
    for (int o = 16; o; o >>= 1) ss += __shfl_xor_sync(0xffffffffu, ss, o);
    if (lane == 0) g_invr[gw] = rsqrtf(ss / (float)NCDIM + 1e-6f);
}

// ---------------- cp.async helpers ----------------
#define CP_ASYNC16(dst, src) asm volatile("cp.async.cg.shared.global [%0], [%1], 16;\n" :: "r"(dst), "l"(src))
#define CP_COMMIT() asm volatile("cp.async.commit_group;\n" ::)
#define CP_WAIT(N_) asm volatile("cp.async.wait_group %0;\n" :: "n"(N_))

__device__ __forceinline__ float gelu_exact(float v) {
    return 0.5f * v * (1.0f + erff(v * 0.70710678118654752f));
}

// ---------------- R6/R8-proven GEMM template (used only for EPI 0: mix) ----------------
template <int EPI>
__global__ void __launch_bounds__(128, 2)
gemm_mma(const float* __restrict__ bias, float* __restrict__ out) {
    constexpr int BM = 128, BK = 32;
    constexpr int BN  = 32;
    constexpr int WMQ = 4, WNQ = 1;
    constexpr int THREADS = WMQ * WNQ * 32;
    constexpr int WM = BM / WMQ, WN = BN / WNQ;
    constexpr int FM = WM / 16, FN = WN / 8;
    constexpr int K  = NCDIM;
    constexpr int KT = K / BK;
    constexpr int ACH = BM * BK / 8, BCH = BN * BK / 8;
    constexpr int APT = ACH / THREADS;
    constexpr int BPT = BCH / THREADS;

    const __half* __restrict__ A  = g_xh;
    const __half* __restrict__ Bt = g_phit;

    __shared__ alignas(16) __half sA[2][BM * BK];
    __shared__ alignas(16) __half sB[2][BN * BK];
    uint32_t sAb = (uint32_t)__cvta_generic_to_shared(&sA[0][0]);
    uint32_t sBb = (uint32_t)__cvta_generic_to_shared(&sB[0][0]);

    const int tid = threadIdx.x;
    const int mBase = blockIdx.y * BM;
    const int nBase = blockIdx.x * BN;

    auto loadTiles = [&](int stg, int kt) {
        int k0 = kt * BK;
        #pragma unroll
        for (int it = 0; it < APT; it++) {
            int ch = tid + it * THREADS;
            int row = ch >> 2, k8 = ch & 3;
            const __half* g = A + (size_t)(mBase + row) * K + k0 + k8 * 8;
            uint32_t d = sAb + 2 * (stg * BM * BK + row * BK + ((k8 ^ ((row >> 1) & 3)) << 3));
            CP_ASYNC16(d, g);
        }
        #pragma unroll
        for (int it = 0; it < BPT; it++) {
            int ch = tid + it * THREADS;
            int row = ch >> 2, k8 = ch & 3;
            const __half* g = Bt + (size_t)(nBase + row) * K + k0 + k8 * 8;
            uint32_t d = sBb + 2 * (stg * BN * BK + row * BK + ((k8 ^ ((row >> 1) & 3)) << 3));
            CP_ASYNC16(d, g);
        }
    };

    const int warp = tid >> 5, lane = tid & 31;
    const int wm = warp / WNQ, wn = warp % WNQ;

    float acc[FM][FN][4];
    #pragma unroll
    for (int i = 0; i < FM; i++)
        #pragma unroll
        for (int j = 0; j < FN; j++)
            #pragma unroll
            for (int q = 0; q < 4; q++) acc[i][j][q] = 0.f;

    const int aRow = lane & 15;
    const int aKc  = lane >> 4;
    const int bRow = lane & 7;
    const int bKc  = (lane >> 3) & 1;

    loadTiles(0, 0);
    CP_COMMIT();
    for (int kt = 0; kt < KT; kt++) {
        int cur = kt & 1;
        if (kt + 1 < KT) { loadTiles(cur ^ 1, kt + 1); CP_COMMIT(); CP_WAIT(1); }
        else             { CP_WAIT(0); }
        __syncthreads();

        #pragma unroll
        for (int ks = 0; ks < 2; ks++) {
            uint32_t a[FM][4];
            uint32_t b[FN][2];
            #pragma unroll
            for (int fm = 0; fm < FM; fm++) {
                int row = wm * WM + fm * 16 + aRow;
                int k8  = ks * 2 + aKc;
                uint32_t ad = sAb + 2 * (cur * BM * BK + row * BK + ((k8 ^ ((row >> 1) & 3)) << 3));
                asm volatile("ldmatrix.sync.aligned.m8n8.x4.shared.b16 {%0,%1,%2,%3}, [%4];\n"
                             : "=r"(a[fm][0]), "=r"(a[fm][1]), "=r"(a[fm][2]), "=r"(a[fm][3])
                             : "r"(ad));
            }
            #pragma unroll
            for (int fn = 0; fn < FN; fn++) {
                int row = wn * WN + fn * 8 + bRow;
                int k8  = ks * 2 + bKc;
                uint32_t bd = sBb + 2 * (cur * BN * BK + row * BK + ((k8 ^ ((row >> 1) & 3)) << 3));
                asm volatile("ldmatrix.sync.aligned.m8n8.x2.shared.b16 {%0,%1}, [%2];\n"
                             : "=r"(b[fn][0]), "=r"(b[fn][1])
                             : "r"(bd));
            }
            #pragma unroll
            for (int fm = 0; fm < FM; fm++)
                #pragma unroll
                for (int fn = 0; fn < FN; fn++) {
                    asm volatile(
                        "mma.sync.aligned.m16n8k16.row.col.f32.f16.f16.f32 "
                        "{%0,%1,%2,%3}, {%4,%5,%6,%7}, {%8,%9}, {%0,%1,%2,%3};\n"
                        : "+f"(acc[fm][fn][0]), "+f"(acc[fm][fn][1]),
                          "+f"(acc[fm][fn][2]), "+f"(acc[fm][fn][3])
                        : "r"(a[fm][0]), "r"(a[fm][1]), "r"(a[fm][2]), "r"(a[fm][3]),
                          "r"(b[fn][0]), "r"(b[fn][1]));
                }
        }
        __syncthreads();
    }

    const int gq = lane >> 2, cq = lane & 3;
    #pragma unroll
    for (int fm = 0; fm < FM; fm++)
        #pragma unroll
        for (int fn = 0; fn < FN; fn++) {
            int r0 = mBase + wm * WM + fm * 16 + gq;
            int c0 = nBase + wn * WN + fn * 8 + cq * 2;
            float2* o = (float2*)g_mix;
            o[((size_t)r0 * 32 + c0) >> 1]       = make_float2(acc[fm][fn][0], acc[fm][fn][1]);
            o[((size_t)(r0 + 8) * 32 + c0) >> 1] = make_float2(acc[fm][fn][2], acc[fm][fn][3]);
        }
}

// ================= big GEMM: BM=128, BN=128, BK=64, 3-stage, trans-B =================
// A: [m][k] k-contiguous (g_xinh / g_hidh), normal ldmatrix (R8-proven path).
// B: native row-major weight [k][n] n-contiguous (g_w1h / g_w2h), ldmatrix.x2.trans.
//    smem B tile: [64 k-rows][128 n-cols] fp16 = 256B rows, 16 chunks, swizzle c^(k&7).
// EPI 1: hid = gelu(xin@W1 + b1) -> g_hidh (fp16).           K=768,  WN=3072
// EPI 2: out = hres@x + hpost*(hid@W2 + b2) (fused scatter). K=3072, WN=768
#define HP_STAGES 3
#define HP_STG_BYTES (256 * 64 * 2)   // A(128x64) 16KB + B(64x128) 16KB per stage

template <int KDIM, int EPI>
__global__ void __launch_bounds__(256, 2)
gemm_hp(const float* __restrict__ bias, float* __restrict__ out) {
    constexpr int BM = 128, BK = 64;
    constexpr int KT = KDIM / BK;
    constexpr int WN = (EPI == 1) ? DFFDIM : CDIM;   // weight row length (n-dim)

    const __half* __restrict__ A  = (EPI == 1) ? g_xinh : g_hidh;
    const __half* __restrict__ Bw = (EPI == 1) ? g_w1h  : g_w2h;

    extern __shared__ char smem_raw[];
    uint32_t sAb = (uint32_t)__cvta_generic_to_shared(smem_raw);

    const int tid = threadIdx.x, warp = tid >> 5, lane = tid & 31;
    const int mBase = blockIdx.y * BM;
    const int nBase = blockIdx.x * 128;
    const int wm = warp >> 2, wn = warp & 3;     // 2x4 warps, each 64x32

    auto loadTiles = [&](int stg, int kt) {
        int k0 = kt * BK;
        uint32_t sb = sAb + stg * HP_STG_BYTES;
        #pragma unroll
        for (int it = 0; it < 4; it++) {          // A: 128 rows x 8 chunks (128B rows)
            int ch = tid + it * 256;
            int row = ch >> 3, c = ch & 7;
            const __half* g = A + (size_t)(mBase + row) * KDIM + k0 + c * 8;
            CP_ASYNC16(sb + row * 128 + ((c ^ (row & 7)) << 4), g);
        }
        #pragma unroll
        for (int it = 0; it < 4; it++) {          // B: 64 k-rows x 16 chunks (256B rows)
            int ch = tid + it * 256;
            int row = ch >> 4, c = ch & 15;
            const __half* g = Bw + (size_t)(k0 + row) * WN + nBase + c * 8;
            CP_ASYNC16(sb + 16384 + row * 256 + ((c ^ (row & 7)) << 4), g);
        }
    };

    const int aRow = lane & 15, aKc = lane >> 4;

    float acc[4][4][4];
    #pragma unroll
    for (int i = 0; i < 4; i++)
        #pragma unroll
        for (int j = 0; j < 4; j++)
            #pragma unroll
            for (int q = 0; q < 4; q++) acc[i][j][q] = 0.f;

    loadTiles(0, 0); CP_COMMIT();
    loadTiles(1, 1); CP_COMMIT();

    for (int kt = 0; kt < KT; kt++) {
        int cur = kt % 3;
        if (kt + 2 < KT) { loadTiles((kt + 2) % 3, kt + 2); CP_COMMIT(); CP_WAIT(2); }
        else             { CP_WAIT(0); }
        __syncthreads();

        uint32_t sb = sAb + cur * HP_STG_BYTES;
        #pragma unroll
        for (int ks = 0; ks < 4; ks++) {
            uint32_t a[4][4], b[4][2];
            #pragma unroll
            for (int fm = 0; fm < 4; fm++) {
                int row = wm * 64 + fm * 16 + aRow;
                int c = ks * 2 + aKc;
                uint32_t ad = sb + row * 128 + ((c ^ (row & 7)) << 4);
                asm volatile("ldmatrix.sync.aligned.m8n8.x4.shared.b16 {%0,%1,%2,%3}, [%4];\n"
                             : "=r"(a[fm][0]), "=r"(a[fm][1]), "=r"(a[fm][2]), "=r"(a[fm][3])
                             : "r"(ad));
            }
            // B: trans ldmatrix from [k][n] tile. lanes 0-7 -> k=ks*16+0..7 (b0),
            // lanes 8-15 -> k=ks*16+8..15 (b1); each addr = 16B row at n-block column.
            {
                int krow = ks * 16 + (lane & 15);
                #pragma unroll
                for (int fn = 0; fn < 4; fn++) {
                    int chunkN = (wn * 32 + fn * 8) >> 3;        // 16B chunk along n
                    uint32_t bd = sb + 16384 + krow * 256 + ((chunkN ^ (krow & 7)) << 4);
                    asm volatile("ldmatrix.sync.aligned.m8n8.x2.trans.shared.b16 {%0,%1}, [%2];\n"
                                 : "=r"(b[fn][0]), "=r"(b[fn][1])
                                 : "r"(bd));
                }
            }
            #pragma unroll
            for (int fm = 0; fm < 4; fm++)
                #pragma unroll
                for (int fn = 0; fn < 4; fn++)
                    asm volatile(
                        "mma.sync.aligned.m16n8k16.row.col.f32.f16.f16.f32 "
                        "{%0,%1,%2,%3}, {%4,%5,%6,%7}, {%8,%9}, {%0,%1,%2,%3};\n"
                        : "+f"(acc[fm][fn][0]), "+f"(acc[fm][fn][1]),
                          "+f"(acc[fm][fn][2]), "+f"(acc[fm][fn][3])
                        : "r"(a[fm][0]), "r"(a[fm][1]), "r"(a[fm][2]), "r"(a[fm][3]),
                          "r"(b[fn][0]), "r"(b[fn][1]));
        }
        __syncthreads();
    }

    // ---------------- epilogues (verbatim from R6/R8-proven) ----------------
    const int gq = lane >> 2, cq = lane & 3;
    if constexpr (EPI == 1) {
        #pragma unroll
        for (int fm = 0; fm < 4; fm++)
            #pragma unroll
            for (int fn = 0; fn < 4; fn++) {
                int r0 = mBase + wm * 64 + fm * 16 + gq;
                int c0 = nBase + wn * 32 + fn * 8 + cq * 2;
                float bz0 = bias[c0], bz1 = bias[c0 + 1];
                float v0 = gelu_exact(acc[fm][fn][0] + bz0);
                float v1 = gelu_exact(acc[fm][fn][1] + bz1);
                float v2 = gelu_exact(acc[fm][fn][2] + bz0);
                float v3 = gelu_exact(acc[fm][fn][3] + bz1);
                __half2* o = (__half2*)g_hidh;
                o[((size_t)r0 * DFFDIM + c0) >> 1]       = __floats2half2_rn(v0, v1);
                o[((size_t)(r0 + 8) * DFFDIM + c0) >> 1] = __floats2half2_rn(v2, v3);
            }
    } else {
        #pragma unroll
        for (int fm = 0; fm < 4; fm++) {
            int r0 = mBase + wm * 64 + fm * 16 + gq;
            int r1 = r0 + 8;
            float hp0[4], hp1[4], hr0[16], hr1[16];
            #pragma unroll
            for (int n = 0; n < 4; n++) { hp0[n] = g_hpost[r0 * 4 + n]; hp1[n] = g_hpost[r1 * 4 + n]; }
            #pragma unroll
            for (int i = 0; i < 16; i++) { hr0[i] = g_hres[r0 * 16 + i]; hr1[i] = g_hres[r1 * 16 + i]; }
            #pragma unroll
            for (int fn = 0; fn < 4; fn++) {
                int c0 = nBase + wn * 32 + fn * 8 + cq * 2;
                float bz0 = bias[c0], bz1 = bias[c0 + 1];
                float f0x = acc[fm][fn][0] + bz0, f0y = acc[fm][fn][1] + bz1;
                float f1x = acc[fm][fn][2] + bz0, f1y = acc[fm][fn][3] + bz1;
                float2 x0[4], x1[4];
                #pragma unroll
                for (int j = 0; j < 4; j++) {
                    x0[j] = __half22float2(*(const __half2*)(g_xh + (size_t)r0 * NCDIM + j * CDIM + c0));
                    x1[j] = __half22float2(*(const __half2*)(g_xh + (size_t)r1 * NCDIM + j * CDIM + c0));
                }
                #pragma unroll
                for (int n = 0; n < 4; n++) {
                    float ox = hp0[n] * f0x, oy = hp0[n] * f0y;
                    #pragma unroll
                    for (int j = 0; j < 4; j++) {
                        ox += hr0[n * 4 + j] * x0[j].x;
                        oy += hr0[n * 4 + j] * x0[j].y;
                    }
                    *(float2*)(out + ((size_t)r0 * 4 + n) * CDIM + c0) = make_float2(ox, oy);
                }
                #pragma unroll
                for (int n = 0; n < 4; n++) {
                    float ox = hp1[n] * f1x, oy = hp1[n] * f1y;
                    #pragma unroll
                    for (int j = 0; j < 4; j++) {
                        ox += hr1[n * 4 + j] * x1[j].x;
                        oy += hr1[n * 4 + j] * x1[j].y;
                    }
                    *(float2*)(out + ((size_t)r1 * 4 + n) * CDIM + c0) = make_float2(ox, oy);
                }
            }
        }
    }
}

// ---------------- routing (sigmoid / sinkhorn), fast-math intrinsics ----------------
__global__ void routing_kernel(const float* __restrict__ b,
                               const float* __restrict__ apre,
                               const float* __restrict__ apost,
                               const float* __restrict__ ares) {
    int t = blockIdx.x * blockDim.x + threadIdx.x;
    if (t >= TOK) return;
    float invr = g_invr[t];
    float m[24];
    #pragma unroll
    for (int i = 0; i < 24; i++) m[i] = g_mix[(size_t)t * 32 + i] * invr;
    float ap = apre[0], apo = apost[0], ar = ares[0];
    #pragma unroll
    for (int n = 0; n < 4; n++)
        g_hpre[t * 4 + n] = __fdividef(1.0f, 1.0f + __expf(-(m[n] * ap + b[n])));
    #pragma unroll
    for (int n = 0; n < 4; n++)
        g_hpost[t * 4 + n] = __fdividef(2.0f, 1.0f + __expf(-(m[4 + n] * apo + b[4 + n])));
    float r[16];
    #pragma unroll
    for (int i = 0; i < 16; i++) r[i] = m[8 + i] * ar + b[8 + i];
    #pragma unroll
    for (int row = 0; row < 4; row++) {
        float mx = r[row * 4];
        #pragma unroll
        for (int j = 1; j < 4; j++) mx = fmaxf(mx, r[row * 4 + j]);
        #pragma unroll
        for (int j = 0; j < 4; j++) r[row * 4 + j] = __expf(r[row * 4 + j] - mx);
    }
    for (int it = 0; it < 20; it++) {
        #pragma unroll
        for (int row = 0; row < 4; row++) {
            float inv = __fdividef(1.0f, r[row * 4] + r[row * 4 + 1] + r[row * 4 + 2] + r[row * 4 + 3] + 1e-6f);
            #pragma unroll
            for (int j = 0; j < 4; j++) r[row * 4 + j] *= inv;
        }
        #pragma unroll
        for (int col = 0; col < 4; col++) {
            float inv = __fdividef(1.0f, r[col] + r[4 + col] + r[8 + col] + r[12 + col] + 1e-6f);
            #pragma unroll
            for (int row = 0; row < 4; row++) r[row * 4 + col] *= inv;
        }
    }
    #pragma unroll
    for (int i = 0; i < 16; i++) g_hres[t * 16 + i] = r[i];
}

// ---------------- x_in = sum_n h_pre[n] * x[n,:] ----------------
__global__ void xin_kernel() {
    int idx = blockIdx.x * blockDim.x + threadIdx.x;
    if (idx >= TOK * 384) return;
    int t = idx / 384, c2 = idx % 384;
    const __half2* xh2 = (const __half2*)g_xh;
    float ax = 0.f, ay = 0.f;
    #pragma unroll
    for (int n = 0; n < 4; n++) {
        float2 v = __half22float2(xh2[(size_t)t * 1536 + n * 384 + c2]);
        float h = g_hpre[t * 4 + n];
        ax += h * v.x; ay += h * v.y;
    }
    ((__half2*)g_xinh)[(size_t)t * 384 + c2] = __floats2half2_rn(ax, ay);
}

// ---------------- launch ----------------
extern "C" void kernel_launch(void* const* d_in, const int* in_sizes, int n_in,
                              void* d_out, int out_size) {
    const float* x     = (const float*)d_in[0];
    const float* phi   = (const float*)d_in[1];
    const float* b     = (const float*)d_in[2];
    const float* apre  = (const float*)d_in[3];
    const float* apost = (const float*)d_in[4];
    const float* ares  = (const float*)d_in[5];
    const float* W1    = (const float*)d_in[6];
    const float* b1    = (const float*)d_in[7];
    const float* W2    = (const float*)d_in[8];
    const float* b2    = (const float*)d_in[9];
    float* out = (float*)d_out;

    const int dyn_smem = HP_STAGES * HP_STG_BYTES;   // 96 KB
    cudaFuncSetAttribute(gemm_hp<CDIM, 1>,  cudaFuncAttributeMaxDynamicSharedMemorySize, dyn_smem);
    cudaFuncSetAttribute(gemm_hp<NCDIM, 2>, cudaFuncAttributeMaxDynamicSharedMemorySize, dyn_smem);

    convert_w_kernel<<<1024, 256>>>(W1, W2, phi);
    sumsq_convert_kernel<<<TOK / 8, 256>>>(x);
    gemm_mma<0><<<dim3(1, TOK / 128), 128>>>(nullptr, nullptr);
    routing_kernel<<<TOK / 128, 128>>>(b, apre, apost, ares);
    xin_kernel<<<TOK * 384 / 256, 256>>>();
    gemm_hp<CDIM, 1><<<dim3(DFFDIM / 128, TOK / 128), 256, dyn_smem>>>(b1, nullptr);
    gemm_hp<NCDIM, 2><<<dim3(CDIM / 128, TOK / 128), 256, dyn_smem>>>(b2, out);
}

// round 10
// speedup vs baseline: 1.0995x; 1.0139x over previous
#include <cuda_runtime.h>
#include <cuda_fp16.h>
#include <stdint.h>

#define TOK 16384
#define CDIM 768
#define NCDIM 3072
#define DFFDIM 3072

// ---------------- device scratch (static; no allocs allowed) ----------------
__device__ __half g_xh[(size_t)TOK * NCDIM];      // x in fp16
__device__ float  g_invr[TOK];
__device__ __half g_phit[32 * NCDIM];             // phi^T padded [32][3072]
__device__ __half g_w1h[(size_t)CDIM * DFFDIM];   // W1 fp16, native [768][3072]
__device__ __half g_w2h[(size_t)DFFDIM * CDIM];   // W2 fp16, native [3072][768]
__device__ float  g_hpre[TOK * 4];
__device__ float  g_hpost[TOK * 4];
__device__ float  g_hres[TOK * 16];
__device__ __half g_xinh[(size_t)TOK * CDIM];     // pre-aggregated stream, fp16
__device__ __half g_hidh[(size_t)TOK * DFFDIM];   // gelu(x_in@W1+b1), fp16

// ---------------- kernel 1: rms sumsq + fp32->fp16 convert + phi pad ----------------
__global__ void sumsq_convert_kernel(const float* __restrict__ x,
                                     const float* __restrict__ phi) {
    int gid = blockIdx.x * blockDim.x + threadIdx.x;
    if (gid < 32 * NCDIM) {
        int j = gid / NCDIM, k = gid % NCDIM;
        g_phit[gid] = (j < 24) ? __float2half(phi[k * 24 + j]) : __float2half(0.0f);
    }
    int gw = gid >> 5;
    int lane = threadIdx.x & 31;
    if (gw >= TOK) return;
    const float4* row = (const float4*)(x + (size_t)gw * NCDIM);
    __half2* outrow = (__half2*)(g_xh + (size_t)gw * NCDIM);
    float ss = 0.f;
    #pragma unroll 4
    for (int i = lane; i < NCDIM / 4; i += 32) {
        float4 v = row[i];
        ss += v.x * v.x + v.y * v.y + v.z * v.z + v.w * v.w;
        outrow[2 * i]     = __floats2half2_rn(v.x, v.y);
        outrow[2 * i + 1] = __floats2half2_rn(v.z, v.w);
    }
    #pragma unroll
    for (int o = 16; o; o >>= 1) ss += __shfl_xor_sync(0xffffffffu, ss, o);
    if (lane == 0) g_invr[gw] = rsqrtf(ss / (float)NCDIM + 1e-6f);
}

// ---------------- cp.async helpers ----------------
#define CP_ASYNC16(dst, src) asm volatile("cp.async.cg.shared.global [%0], [%1], 16;\n" :: "r"(dst), "l"(src))
#define CP_COMMIT() asm volatile("cp.async.commit_group;\n" ::)
#define CP_WAIT(N_) asm volatile("cp.async.wait_group %0;\n" :: "n"(N_))

__device__ __forceinline__ float gelu_exact(float v) {
    return 0.5f * v * (1.0f + erff(v * 0.70710678118654752f));
}

// ============ kernel 2: fused mix GEMM (BM=64) + routing epilogue + weight convert ============
// blocks 0..255   : mix = x_h @ phi_t for 64 tokens, then sigmoid/sinkhorn in-kernel.
// blocks 256..767 : fp32->fp16 weight conversion (1:1 coalesced), overlapped with mix.
#define MIXBLKS 256
#define CONVBLKS 512

__global__ void __launch_bounds__(128, 2)
mix_routing_conv_kernel(const float* __restrict__ W1, const float* __restrict__ W2,
                        const float* __restrict__ b,  const float* __restrict__ apre,
                        const float* __restrict__ apost, const float* __restrict__ ares) {
    if (blockIdx.x >= MIXBLKS) {
        // ---- weight conversion path ----
        int i = (blockIdx.x - MIXBLKS) * 128 + threadIdx.x;
        const int stride = CONVBLKS * 128;
        const int WELEM4 = (CDIM * DFFDIM) / 4;
        for (int idx = i; idx < WELEM4; idx += stride) {
            float4 v = ((const float4*)W1)[idx];
            ((__half2*)g_w1h)[2 * idx]     = __floats2half2_rn(v.x, v.y);
            ((__half2*)g_w1h)[2 * idx + 1] = __floats2half2_rn(v.z, v.w);
            float4 w = ((const float4*)W2)[idx];
            ((__half2*)g_w2h)[2 * idx]     = __floats2half2_rn(w.x, w.y);
            ((__half2*)g_w2h)[2 * idx + 1] = __floats2half2_rn(w.z, w.w);
        }
        return;
    }

    // ---- mix GEMM path: BM=64, BN=32, BK=32, 2-stage (proven template, WM 32->16) ----
    constexpr int BM = 64, BK = 32, BN = 32;
    constexpr int THREADS = 128;
    constexpr int K = NCDIM, KT = K / BK;
    const __half* __restrict__ A  = g_xh;
    const __half* __restrict__ Bt = g_phit;

    __shared__ alignas(16) __half sA[2][BM * BK];
    __shared__ alignas(16) __half sB[2][BN * BK];
    __shared__ float smix[64][25];                 // cols 0..23 staged for routing
    uint32_t sAb = (uint32_t)__cvta_generic_to_shared(&sA[0][0]);
    uint32_t sBb = (uint32_t)__cvta_generic_to_shared(&sB[0][0]);

    const int tid = threadIdx.x;
    const int mBase = blockIdx.x * BM;

    auto loadTiles = [&](int stg, int kt) {
        int k0 = kt * BK;
        #pragma unroll
        for (int it = 0; it < 2; it++) {           // A: 64 rows x 4 chunks = 256
            int ch = tid + it * THREADS;
            int row = ch >> 2, k8 = ch & 3;
            const __half* g = A + (size_t)(mBase + row) * K + k0 + k8 * 8;
            uint32_t d = sAb + 2 * (stg * BM * BK + row * BK + ((k8 ^ ((row >> 1) & 3)) << 3));
            CP_ASYNC16(d, g);
        }
        {                                          // B: 32 rows x 4 chunks = 128
            int ch = tid;
            int row = ch >> 2, k8 = ch & 3;
            const __half* g = Bt + (size_t)row * K + k0 + k8 * 8;
            uint32_t d = sBb + 2 * (stg * BN * BK + row * BK + ((k8 ^ ((row >> 1) & 3)) << 3));
            CP_ASYNC16(d, g);
        }
    };

    const int warp = tid >> 5, lane = tid & 31;
    float acc[4][4];                               // FM=1: [fn][q]
    #pragma unroll
    for (int j = 0; j < 4; j++)
        #pragma unroll
        for (int q = 0; q < 4; q++) acc[j][q] = 0.f;

    const int aRow = lane & 15, aKc = lane >> 4;
    const int bRow = lane & 7,  bKc = (lane >> 3) & 1;

    loadTiles(0, 0);
    CP_COMMIT();
    for (int kt = 0; kt < KT; kt++) {
        int cur = kt & 1;
        if (kt + 1 < KT) { loadTiles(cur ^ 1, kt + 1); CP_COMMIT(); CP_WAIT(1); }
        else             { CP_WAIT(0); }
        __syncthreads();
        #pragma unroll
        for (int ks = 0; ks < 2; ks++) {
            uint32_t a[4], bfr[4][2];
            {
                int row = warp * 16 + aRow;        // warp owns one 16-row band
                int k8 = ks * 2 + aKc;
                uint32_t ad = sAb + 2 * (cur * BM * BK + row * BK + ((k8 ^ ((row >> 1) & 3)) << 3));
                asm volatile("ldmatrix.sync.aligned.m8n8.x4.shared.b16 {%0,%1,%2,%3}, [%4];\n"
                             : "=r"(a[0]), "=r"(a[1]), "=r"(a[2]), "=r"(a[3]) : "r"(ad));
            }
            #pragma unroll
            for (int fn = 0; fn < 4; fn++) {
                int row = fn * 8 + bRow;
                int k8 = ks * 2 + bKc;
                uint32_t bd = sBb + 2 * (cur * BN * BK + row * BK + ((k8 ^ ((row >> 1) & 3)) << 3));
                asm volatile("ldmatrix.sync.aligned.m8n8.x2.shared.b16 {%0,%1}, [%2];\n"
                             : "=r"(bfr[fn][0]), "=r"(bfr[fn][1]) : "r"(bd));
            }
            #pragma unroll
            for (int fn = 0; fn < 4; fn++)
                asm volatile(
                    "mma.sync.aligned.m16n8k16.row.col.f32.f16.f16.f32 "
                    "{%0,%1,%2,%3}, {%4,%5,%6,%7}, {%8,%9}, {%0,%1,%2,%3};\n"
                    : "+f"(acc[fn][0]), "+f"(acc[fn][1]), "+f"(acc[fn][2]), "+f"(acc[fn][3])
                    : "r"(a[0]), "r"(a[1]), "r"(a[2]), "r"(a[3]),
                      "r"(bfr[fn][0]), "r"(bfr[fn][1]));
        }
        __syncthreads();
    }

    // stage mix cols 0..23 to smem (fn=3 covers padded cols 24..31, unused)
    const int gq = lane >> 2, cq = lane & 3;
    {
        int rl0 = warp * 16 + gq, rl1 = rl0 + 8;
        #pragma unroll
        for (int fn = 0; fn < 3; fn++) {
            int c0 = fn * 8 + cq * 2;
            smix[rl0][c0] = acc[fn][0]; smix[rl0][c0 + 1] = acc[fn][1];
            smix[rl1][c0] = acc[fn][2]; smix[rl1][c0 + 1] = acc[fn][3];
        }
    }
    __syncthreads();

    // ---- routing epilogue: one thread per token (tid 0..63) ----
    if (tid < 64) {
        int t = mBase + tid;
        float invr = g_invr[t];
        float m[24];
        #pragma unroll
        for (int i = 0; i < 24; i++) m[i] = smix[tid][i] * invr;
        float ap = apre[0], apo = apost[0], ar = ares[0];
        #pragma unroll
        for (int n = 0; n < 4; n++)
            g_hpre[t * 4 + n] = __fdividef(1.0f, 1.0f + __expf(-(m[n] * ap + b[n])));
        #pragma unroll
        for (int n = 0; n < 4; n++)
            g_hpost[t * 4 + n] = __fdividef(2.0f, 1.0f + __expf(-(m[4 + n] * apo + b[4 + n])));
        float r[16];
        #pragma unroll
        for (int i = 0; i < 16; i++) r[i] = m[8 + i] * ar + b[8 + i];
        #pragma unroll
        for (int row = 0; row < 4; row++) {
            float mx = r[row * 4];
            #pragma unroll
            for (int j = 1; j < 4; j++) mx = fmaxf(mx, r[row * 4 + j]);
            #pragma unroll
            for (int j = 0; j < 4; j++) r[row * 4 + j] = __expf(r[row * 4 + j] - mx);
        }
        for (int it = 0; it < 20; it++) {
            #pragma unroll
            for (int row = 0; row < 4; row++) {
                float inv = __fdividef(1.0f, r[row * 4] + r[row * 4 + 1] + r[row * 4 + 2] + r[row * 4 + 3] + 1e-6f);
                #pragma unroll
                for (int j = 0; j < 4; j++) r[row * 4 + j] *= inv;
            }
            #pragma unroll
            for (int col = 0; col < 4; col++) {
                float inv = __fdividef(1.0f, r[col] + r[4 + col] + r[8 + col] + r[12 + col] + 1e-6f);
                #pragma unroll
                for (int row = 0; row < 4; row++) r[row * 4 + col] *= inv;
            }
        }
        #pragma unroll
        for (int i = 0; i < 16; i++) g_hres[t * 16 + i] = r[i];
    }
}

// ---------------- kernel 3: x_in = sum_n h_pre[n] * x[n,:] ----------------
__global__ void xin_kernel() {
    int idx = blockIdx.x * blockDim.x + threadIdx.x;
    if (idx >= TOK * 384) return;
    int t = idx / 384, c2 = idx % 384;
    const __half2* xh2 = (const __half2*)g_xh;
    float ax = 0.f, ay = 0.f;
    #pragma unroll
    for (int n = 0; n < 4; n++) {
        float2 v = __half22float2(xh2[(size_t)t * 1536 + n * 384 + c2]);
        float h = g_hpre[t * 4 + n];
        ax += h * v.x; ay += h * v.y;
    }
    ((__half2*)g_xinh)[(size_t)t * 384 + c2] = __floats2half2_rn(ax, ay);
}

// ================= big GEMM: BM=128, BN=128, BK=64, 3-stage, trans-B (R9-proven) =================
#define HP_STAGES 3
#define HP_STG_BYTES (256 * 64 * 2)   // A(128x64) 16KB + B(64x128) 16KB per stage

template <int KDIM, int EPI>
__global__ void __launch_bounds__(256, 2)
gemm_hp(const float* __restrict__ bias, float* __restrict__ out) {
    constexpr int BM = 128, BK = 64;
    constexpr int KT = KDIM / BK;
    constexpr int WN = (EPI == 1) ? DFFDIM : CDIM;   // weight row length (n-dim)

    const __half* __restrict__ A  = (EPI == 1) ? g_xinh : g_hidh;
    const __half* __restrict__ Bw = (EPI == 1) ? g_w1h  : g_w2h;

    extern __shared__ char smem_raw[];
    uint32_t sAb = (uint32_t)__cvta_generic_to_shared(smem_raw);

    const int tid = threadIdx.x, warp = tid >> 5, lane = tid & 31;
    const int mBase = blockIdx.y * BM;
    const int nBase = blockIdx.x * 128;
    const int wm = warp >> 2, wn = warp & 3;     // 2x4 warps, each 64x32

    auto loadTiles = [&](int stg, int kt) {
        int k0 = kt * BK;
        uint32_t sb = sAb + stg * HP_STG_BYTES;
        #pragma unroll
        for (int it = 0; it < 4; it++) {          // A: 128 rows x 8 chunks (128B rows)
            int ch = tid + it * 256;
            int row = ch >> 3, c = ch & 7;
            const __half* g = A + (size_t)(mBase + row) * KDIM + k0 + c * 8;
            CP_ASYNC16(sb + row * 128 + ((c ^ (row & 7)) << 4), g);
        }
        #pragma unroll
        for (int it = 0; it < 4; it++) {          // B: 64 k-rows x 16 chunks (256B rows)
            int ch = tid + it * 256;
            int row = ch >> 4, c = ch & 15;
            const __half* g = Bw + (size_t)(k0 + row) * WN + nBase + c * 8;
            CP_ASYNC16(sb + 16384 + row * 256 + ((c ^ (row & 7)) << 4), g);
        }
    };

    const int aRow = lane & 15, aKc = lane >> 4;

    float acc[4][4][4];
    #pragma unroll
    for (int i = 0; i < 4; i++)
        #pragma unroll
        for (int j = 0; j < 4; j++)
            #pragma unroll
            for (int q = 0; q < 4; q++) acc[i][j][q] = 0.f;

    loadTiles(0, 0); CP_COMMIT();
    loadTiles(1, 1); CP_COMMIT();

    for (int kt = 0; kt < KT; kt++) {
        int cur = kt % 3;
        if (kt + 2 < KT) { loadTiles((kt + 2) % 3, kt + 2); CP_COMMIT(); CP_WAIT(2); }
        else             { CP_WAIT(0); }
        __syncthreads();

        uint32_t sb = sAb + cur * HP_STG_BYTES;
        #pragma unroll
        for (int ks = 0; ks < 4; ks++) {
            uint32_t a[4][4], b[4][2];
            #pragma unroll
            for (int fm = 0; fm < 4; fm++) {
                int row = wm * 64 + fm * 16 + aRow;
                int c = ks * 2 + aKc;
                uint32_t ad = sb + row * 128 + ((c ^ (row & 7)) << 4);
                asm volatile("ldmatrix.sync.aligned.m8n8.x4.shared.b16 {%0,%1,%2,%3}, [%4];\n"
                             : "=r"(a[fm][0]), "=r"(a[fm][1]), "=r"(a[fm][2]), "=r"(a[fm][3])
                             : "r"(ad));
            }
            {
                int krow = ks * 16 + (lane & 15);
                #pragma unroll
                for (int fn = 0; fn < 4; fn++) {
                    int chunkN = (wn * 32 + fn * 8) >> 3;        // 16B chunk along n
                    uint32_t bd = sb + 16384 + krow * 256 + ((chunkN ^ (krow & 7)) << 4);
                    asm volatile("ldmatrix.sync.aligned.m8n8.x2.trans.shared.b16 {%0,%1}, [%2];\n"
                                 : "=r"(b[fn][0]), "=r"(b[fn][1])
                                 : "r"(bd));
                }
            }
            #pragma unroll
            for (int fm = 0; fm < 4; fm++)
                #pragma unroll
                for (int fn = 0; fn < 4; fn++)
                    asm volatile(
                        "mma.sync.aligned.m16n8k16.row.col.f32.f16.f16.f32 "
                        "{%0,%1,%2,%3}, {%4,%5,%6,%7}, {%8,%9}, {%0,%1,%2,%3};\n"
                        : "+f"(acc[fm][fn][0]), "+f"(acc[fm][fn][1]),
                          "+f"(acc[fm][fn][2]), "+f"(acc[fm][fn][3])
                        : "r"(a[fm][0]), "r"(a[fm][1]), "r"(a[fm][2]), "r"(a[fm][3]),
                          "r"(b[fn][0]), "r"(b[fn][1]));
        }
        __syncthreads();
    }

    // ---------------- epilogues (R6/R8/R9-proven) ----------------
    const int gq = lane >> 2, cq = lane & 3;
    if constexpr (EPI == 1) {
        #pragma unroll
        for (int fm = 0; fm < 4; fm++)
            #pragma unroll
            for (int fn = 0; fn < 4; fn++) {
                int r0 = mBase + wm * 64 + fm * 16 + gq;
                int c0 = nBase + wn * 32 + fn * 8 + cq * 2;
                float bz0 = bias[c0], bz1 = bias[c0 + 1];
                float v0 = gelu_exact(acc[fm][fn][0] + bz0);
                float v1 = gelu_exact(acc[fm][fn][1] + bz1);
                float v2 = gelu_exact(acc[fm][fn][2] + bz0);
                float v3 = gelu_exact(acc[fm][fn][3] + bz1);
                __half2* o = (__half2*)g_hidh;
                o[((size_t)r0 * DFFDIM + c0) >> 1]       = __floats2half2_rn(v0, v1);
                o[((size_t)(r0 + 8) * DFFDIM + c0) >> 1] = __floats2half2_rn(v2, v3);
            }
    } else {
        #pragma unroll
        for (int fm = 0; fm < 4; fm++) {
            int r0 = mBase + wm * 64 + fm * 16 + gq;
            int r1 = r0 + 8;
            float hp0[4], hp1[4], hr0[16], hr1[16];
            #pragma unroll
            for (int n = 0; n < 4; n++) { hp0[n] = g_hpost[r0 * 4 + n]; hp1[n] = g_hpost[r1 * 4 + n]; }
            #pragma unroll
            for (int i = 0; i < 16; i++) { hr0[i] = g_hres[r0 * 16 + i]; hr1[i] = g_hres[r1 * 16 + i]; }
            #pragma unroll
            for (int fn = 0; fn < 4; fn++) {
                int c0 = nBase + wn * 32 + fn * 8 + cq * 2;
                float bz0 = bias[c0], bz1 = bias[c0 + 1];
                float f0x = acc[fm][fn][0] + bz0, f0y = acc[fm][fn][1] + bz1;
                float f1x = acc[fm][fn][2] + bz0, f1y = acc[fm][fn][3] + bz1;
                float2 x0[4], x1[4];
                #pragma unroll
                for (int j = 0; j < 4; j++) {
                    x0[j] = __half22float2(*(const __half2*)(g_xh + (size_t)r0 * NCDIM + j * CDIM + c0));
                    x1[j] = __half22float2(*(const __half2*)(g_xh + (size_t)r1 * NCDIM + j * CDIM + c0));
                }
                #pragma unroll
                for (int n = 0; n < 4; n++) {
                    float ox = hp0[n] * f0x, oy = hp0[n] * f0y;
                    #pragma unroll
                    for (int j = 0; j < 4; j++) {
                        ox += hr0[n * 4 + j] * x0[j].x;
                        oy += hr0[n * 4 + j] * x0[j].y;
                    }
                    *(float2*)(out + ((size_t)r0 * 4 + n) * CDIM + c0) = make_float2(ox, oy);
                }
                #pragma unroll
                for (int n = 0; n < 4; n++) {
                    float ox = hp1[n] * f1x, oy = hp1[n] * f1y;
                    #pragma unroll
                    for (int j = 0; j < 4; j++) {
                        ox += hr1[n * 4 + j] * x1[j].x;
                        oy += hr1[n * 4 + j] * x1[j].y;
                    }
                    *(float2*)(out + ((size_t)r1 * 4 + n) * CDIM + c0) = make_float2(ox, oy);
                }
            }
        }
    }
}

// ---------------- launch ----------------
extern "C" void kernel_launch(void* const* d_in, const int* in_sizes, int n_in,
                              void* d_out, int out_size) {
    const float* x     = (const float*)d_in[0];
    const float* phi   = (const float*)d_in[1];
    const float* b     = (const float*)d_in[2];
    const float* apre  = (const float*)d_in[3];
    const float* apost = (const float*)d_in[4];
    const float* ares  = (const float*)d_in[5];
    const float* W1    = (const float*)d_in[6];
    const float* b1    = (const float*)d_in[7];
    const float* W2    = (const float*)d_in[8];
    const float* b2    = (const float*)d_in[9];
    float* out = (float*)d_out;

    const int dyn_smem = HP_STAGES * HP_STG_BYTES;   // 96 KB
    cudaFuncSetAttribute(gemm_hp<CDIM, 1>,  cudaFuncAttributeMaxDynamicSharedMemorySize, dyn_smem);
    cudaFuncSetAttribute(gemm_hp<NCDIM, 2>, cudaFuncAttributeMaxDynamicSharedMemorySize, dyn_smem);

    sumsq_convert_kernel<<<TOK / 8, 256>>>(x, phi);
    mix_routing_conv_kernel<<<MIXBLKS + CONVBLKS, 128>>>(W1, W2, b, apre, apost, ares);
    xin_kernel<<<TOK * 384 / 256, 256>>>();
    gemm_hp<CDIM, 1><<<dim3(DFFDIM / 128, TOK / 128), 256, dyn_smem>>>(b1, nullptr);
    gemm_hp<NCDIM, 2><<<dim3(CDIM / 128, TOK / 128), 256, dyn_smem>>>(b2, out);
}

// round 11
// speedup vs baseline: 1.1445x; 1.0409x over previous
#include <cuda_runtime.h>
#include <cuda_fp16.h>
#include <stdint.h>

#define TOK 16384
#define CDIM 768
#define NCDIM 3072
#define DFFDIM 3072

// ---------------- device scratch (static; no allocs allowed) ----------------
__device__ __half g_xh[(size_t)TOK * NCDIM];      // x in fp16
__device__ float  g_invr[TOK];
__device__ __half g_phit[32 * NCDIM];             // phi^T padded [32][3072]
__device__ __half g_w1h[(size_t)CDIM * DFFDIM];   // W1 fp16, native [768][3072]
__device__ __half g_w2h[(size_t)DFFDIM * CDIM];   // W2 fp16, native [3072][768]
__device__ float  g_hpre[TOK * 4];
__device__ float  g_hpost[TOK * 4];
__device__ float  g_hres[TOK * 16];
__device__ __half g_xinh[(size_t)TOK * CDIM];     // pre-aggregated stream, fp16
__device__ __half g_hidh[(size_t)TOK * DFFDIM];   // gelu(x_in@W1+b1), fp16

// ---------------- kernel 1: rms sumsq + fp32->fp16 convert + phi pad ----------------
__global__ void sumsq_convert_kernel(const float* __restrict__ x,
                                     const float* __restrict__ phi) {
    int gid = blockIdx.x * blockDim.x + threadIdx.x;
    if (gid < 32 * NCDIM) {
        int j = gid / NCDIM, k = gid % NCDIM;
        g_phit[gid] = (j < 24) ? __float2half(phi[k * 24 + j]) : __float2half(0.0f);
    }
    int gw = gid >> 5;
    int lane = threadIdx.x & 31;
    if (gw >= TOK) return;
    const float4* row = (const float4*)(x + (size_t)gw * NCDIM);
    __half2* outrow = (__half2*)(g_xh + (size_t)gw * NCDIM);
    float ss = 0.f;
    #pragma unroll 4
    for (int i = lane; i < NCDIM / 4; i += 32) {
        float4 v = row[i];
        ss += v.x * v.x + v.y * v.y + v.z * v.z + v.w * v.w;
        outrow[2 * i]     = __floats2half2_rn(v.x, v.y);
        outrow[2 * i + 1] = __floats2half2_rn(v.z, v.w);
    }
    #pragma unroll
    for (int o = 16; o; o >>= 1) ss += __shfl_xor_sync(0xffffffffu, ss, o);
    if (lane == 0) g_invr[gw] = rsqrtf(ss / (float)NCDIM + 1e-6f);
}

// ---------------- cp.async helpers ----------------
#define CP_ASYNC16(dst, src) asm volatile("cp.async.cg.shared.global [%0], [%1], 16;\n" :: "r"(dst), "l"(src))
#define CP_COMMIT() asm volatile("cp.async.commit_group;\n" ::)
#define CP_WAIT(N_) asm volatile("cp.async.wait_group %0;\n" :: "n"(N_))

__device__ __forceinline__ float gelu_exact(float v) {
    return 0.5f * v * (1.0f + erff(v * 0.70710678118654752f));
}

// ============ kernel 2: fused mix GEMM (BM=64) + routing epilogue + weight convert ============
#define MIXBLKS 256
#define CONVBLKS 512

__global__ void __launch_bounds__(128, 2)
mix_routing_conv_kernel(const float* __restrict__ W1, const float* __restrict__ W2,
                        const float* __restrict__ b,  const float* __restrict__ apre,
                        const float* __restrict__ apost, const float* __restrict__ ares) {
    if (blockIdx.x >= MIXBLKS) {
        int i = (blockIdx.x - MIXBLKS) * 128 + threadIdx.x;
        const int stride = CONVBLKS * 128;
        const int WELEM4 = (CDIM * DFFDIM) / 4;
        for (int idx = i; idx < WELEM4; idx += stride) {
            float4 v = ((const float4*)W1)[idx];
            ((__half2*)g_w1h)[2 * idx]     = __floats2half2_rn(v.x, v.y);
            ((__half2*)g_w1h)[2 * idx + 1] = __floats2half2_rn(v.z, v.w);
            float4 w = ((const float4*)W2)[idx];
            ((__half2*)g_w2h)[2 * idx]     = __floats2half2_rn(w.x, w.y);
            ((__half2*)g_w2h)[2 * idx + 1] = __floats2half2_rn(w.z, w.w);
        }
        return;
    }

    constexpr int BM = 64, BK = 32, BN = 32;
    constexpr int THREADS = 128;
    constexpr int K = NCDIM, KT = K / BK;
    const __half* __restrict__ A  = g_xh;
    const __half* __restrict__ Bt = g_phit;

    __shared__ alignas(16) __half sA[2][BM * BK];
    __shared__ alignas(16) __half sB[2][BN * BK];
    __shared__ float smix[64][25];
    uint32_t sAb = (uint32_t)__cvta_generic_to_shared(&sA[0][0]);
    uint32_t sBb = (uint32_t)__cvta_generic_to_shared(&sB[0][0]);

    const int tid = threadIdx.x;
    const int mBase = blockIdx.x * BM;

    auto loadTiles = [&](int stg, int kt) {
        int k0 = kt * BK;
        #pragma unroll
        for (int it = 0; it < 2; it++) {
            int ch = tid + it * THREADS;
            int row = ch >> 2, k8 = ch & 3;
            const __half* g = A + (size_t)(mBase + row) * K + k0 + k8 * 8;
            uint32_t d = sAb + 2 * (stg * BM * BK + row * BK + ((k8 ^ ((row >> 1) & 3)) << 3));
            CP_ASYNC16(d, g);
        }
        {
            int ch = tid;
            int row = ch >> 2, k8 = ch & 3;
            const __half* g = Bt + (size_t)row * K + k0 + k8 * 8;
            uint32_t d = sBb + 2 * (stg * BN * BK + row * BK + ((k8 ^ ((row >> 1) & 3)) << 3));
            CP_ASYNC16(d, g);
        }
    };

    const int warp = tid >> 5, lane = tid & 31;
    float acc[4][4];
    #pragma unroll
    for (int j = 0; j < 4; j++)
        #pragma unroll
        for (int q = 0; q < 4; q++) acc[j][q] = 0.f;

    const int aRow = lane & 15, aKc = lane >> 4;
    const int bRow = lane & 7,  bKc = (lane >> 3) & 1;

    loadTiles(0, 0);
    CP_COMMIT();
    for (int kt = 0; kt < KT; kt++) {
        int cur = kt & 1;
        if (kt + 1 < KT) { loadTiles(cur ^ 1, kt + 1); CP_COMMIT(); CP_WAIT(1); }
        else             { CP_WAIT(0); }
        __syncthreads();
        #pragma unroll
        for (int ks = 0; ks < 2; ks++) {
            uint32_t a[4], bfr[4][2];
            {
                int row = warp * 16 + aRow;
                int k8 = ks * 2 + aKc;
                uint32_t ad = sAb + 2 * (cur * BM * BK + row * BK + ((k8 ^ ((row >> 1) & 3)) << 3));
                asm volatile("ldmatrix.sync.aligned.m8n8.x4.shared.b16 {%0,%1,%2,%3}, [%4];\n"
                             : "=r"(a[0]), "=r"(a[1]), "=r"(a[2]), "=r"(a[3]) : "r"(ad));
            }
            #pragma unroll
            for (int fn = 0; fn < 4; fn++) {
                int row = fn * 8 + bRow;
                int k8 = ks * 2 + bKc;
                uint32_t bd = sBb + 2 * (cur * BN * BK + row * BK + ((k8 ^ ((row >> 1) & 3)) << 3));
                asm volatile("ldmatrix.sync.aligned.m8n8.x2.shared.b16 {%0,%1}, [%2];\n"
                             : "=r"(bfr[fn][0]), "=r"(bfr[fn][1]) : "r"(bd));
            }
            #pragma unroll
            for (int fn = 0; fn < 4; fn++)
                asm volatile(
                    "mma.sync.aligned.m16n8k16.row.col.f32.f16.f16.f32 "
                    "{%0,%1,%2,%3}, {%4,%5,%6,%7}, {%8,%9}, {%0,%1,%2,%3};\n"
                    : "+f"(acc[fn][0]), "+f"(acc[fn][1]), "+f"(acc[fn][2]), "+f"(acc[fn][3])
                    : "r"(a[0]), "r"(a[1]), "r"(a[2]), "r"(a[3]),
                      "r"(bfr[fn][0]), "r"(bfr[fn][1]));
        }
        __syncthreads();
    }

    const int gq = lane >> 2, cq = lane & 3;
    {
        int rl0 = warp * 16 + gq, rl1 = rl0 + 8;
        #pragma unroll
        for (int fn = 0; fn < 3; fn++) {
            int c0 = fn * 8 + cq * 2;
            smix[rl0][c0] = acc[fn][0]; smix[rl0][c0 + 1] = acc[fn][1];
            smix[rl1][c0] = acc[fn][2]; smix[rl1][c0 + 1] = acc[fn][3];
        }
    }
    __syncthreads();

    if (tid < 64) {
        int t = mBase + tid;
        float invr = g_invr[t];
        float m[24];
        #pragma unroll
        for (int i = 0; i < 24; i++) m[i] = smix[tid][i] * invr;
        float ap = apre[0], apo = apost[0], ar = ares[0];
        #pragma unroll
        for (int n = 0; n < 4; n++)
            g_hpre[t * 4 + n] = __fdividef(1.0f, 1.0f + __expf(-(m[n] * ap + b[n])));
        #pragma unroll
        for (int n = 0; n < 4; n++)
            g_hpost[t * 4 + n] = __fdividef(2.0f, 1.0f + __expf(-(m[4 + n] * apo + b[4 + n])));
        float r[16];
        #pragma unroll
        for (int i = 0; i < 16; i++) r[i] = m[8 + i] * ar + b[8 + i];
        #pragma unroll
        for (int row = 0; row < 4; row++) {
            float mx = r[row * 4];
            #pragma unroll
            for (int j = 1; j < 4; j++) mx = fmaxf(mx, r[row * 4 + j]);
            #pragma unroll
            for (int j = 0; j < 4; j++) r[row * 4 + j] = __expf(r[row * 4 + j] - mx);
        }
        for (int it = 0; it < 20; it++) {
            #pragma unroll
            for (int row = 0; row < 4; row++) {
                float inv = __fdividef(1.0f, r[row * 4] + r[row * 4 + 1] + r[row * 4 + 2] + r[row * 4 + 3] + 1e-6f);
                #pragma unroll
                for (int j = 0; j < 4; j++) r[row * 4 + j] *= inv;
            }
            #pragma unroll
            for (int col = 0; col < 4; col++) {
                float inv = __fdividef(1.0f, r[col] + r[4 + col] + r[8 + col] + r[12 + col] + 1e-6f);
                #pragma unroll
                for (int row = 0; row < 4; row++) r[row * 4 + col] *= inv;
            }
        }
        #pragma unroll
        for (int i = 0; i < 16; i++) g_hres[t * 16 + i] = r[i];
    }
}

// ---------------- kernel 3: x_in = sum_n h_pre[n] * x[n,:] ----------------
__global__ void xin_kernel() {
    int idx = blockIdx.x * blockDim.x + threadIdx.x;
    if (idx >= TOK * 384) return;
    int t = idx / 384, c2 = idx % 384;
    const __half2* xh2 = (const __half2*)g_xh;
    float ax = 0.f, ay = 0.f;
    #pragma unroll
    for (int n = 0; n < 4; n++) {
        float2 v = __half22float2(xh2[(size_t)t * 1536 + n * 384 + c2]);
        float h = g_hpre[t * 4 + n];
        ax += h * v.x; ay += h * v.y;
    }
    ((__half2*)g_xinh)[(size_t)t * 384 + c2] = __floats2half2_rn(ax, ay);
}

// ================= big GEMM: BM=128, BN=128, BK=64, 3-stage, trans-B =================
// R10 change: 4 warps (2x2), each warp 64x64 (FM=4, FN=8) -> 32 MMAs per ks-step,
// A fragments reused 8x. Loader / pipeline / smem layout / epilogue math unchanged.
#define HP_STAGES 3
#define HP_STG_BYTES (256 * 64 * 2)   // A(128x64) 16KB + B(64x128) 16KB per stage
#define HP_THREADS 128

template <int KDIM, int EPI>
__global__ void __launch_bounds__(HP_THREADS, 2)
gemm_hp(const float* __restrict__ bias, float* __restrict__ out) {
    constexpr int BM = 128, BK = 64;
    constexpr int KT = KDIM / BK;
    constexpr int WN = (EPI == 1) ? DFFDIM : CDIM;   // weight row length (n-dim)

    const __half* __restrict__ A  = (EPI == 1) ? g_xinh : g_hidh;
    const __half* __restrict__ Bw = (EPI == 1) ? g_w1h  : g_w2h;

    extern __shared__ char smem_raw[];
    uint32_t sAb = (uint32_t)__cvta_generic_to_shared(smem_raw);

    const int tid = threadIdx.x, warp = tid >> 5, lane = tid & 31;
    const int mBase = blockIdx.y * BM;
    const int nBase = blockIdx.x * 128;
    const int wm = warp >> 1, wn = warp & 1;     // 2x2 warps, each 64x64

    auto loadTiles = [&](int stg, int kt) {
        int k0 = kt * BK;
        uint32_t sb = sAb + stg * HP_STG_BYTES;
        #pragma unroll
        for (int it = 0; it < 8; it++) {          // A: 128 rows x 8 chunks (128B rows)
            int ch = tid + it * HP_THREADS;
            int row = ch >> 3, c = ch & 7;
            const __half* g = A + (size_t)(mBase + row) * KDIM + k0 + c * 8;
            CP_ASYNC16(sb + row * 128 + ((c ^ (row & 7)) << 4), g);
        }
        #pragma unroll
        for (int it = 0; it < 8; it++) {          // B: 64 k-rows x 16 chunks (256B rows)
            int ch = tid + it * HP_THREADS;
            int row = ch >> 4, c = ch & 15;
            const __half* g = Bw + (size_t)(k0 + row) * WN + nBase + c * 8;
            CP_ASYNC16(sb + 16384 + row * 256 + ((c ^ (row & 7)) << 4), g);
        }
    };

    const int aRow = lane & 15, aKc = lane >> 4;

    float acc[4][8][4];
    #pragma unroll
    for (int i = 0; i < 4; i++)
        #pragma unroll
        for (int j = 0; j < 8; j++)
            #pragma unroll
            for (int q = 0; q < 4; q++) acc[i][j][q] = 0.f;

    loadTiles(0, 0); CP_COMMIT();
    loadTiles(1, 1); CP_COMMIT();

    for (int kt = 0; kt < KT; kt++) {
        int cur = kt % 3;
        if (kt + 2 < KT) { loadTiles((kt + 2) % 3, kt + 2); CP_COMMIT(); CP_WAIT(2); }
        else             { CP_WAIT(0); }
        __syncthreads();

        uint32_t sb = sAb + cur * HP_STG_BYTES;
        #pragma unroll
        for (int ks = 0; ks < 4; ks++) {
            uint32_t a[4][4], b[8][2];
            #pragma unroll
            for (int fm = 0; fm < 4; fm++) {
                int row = wm * 64 + fm * 16 + aRow;
                int c = ks * 2 + aKc;
                uint32_t ad = sb + row * 128 + ((c ^ (row & 7)) << 4);
                asm volatile("ldmatrix.sync.aligned.m8n8.x4.shared.b16 {%0,%1,%2,%3}, [%4];\n"
                             : "=r"(a[fm][0]), "=r"(a[fm][1]), "=r"(a[fm][2]), "=r"(a[fm][3])
                             : "r"(ad));
            }
            {
                int krow = ks * 16 + (lane & 15);
                #pragma unroll
                for (int fn = 0; fn < 8; fn++) {
                    int chunkN = (wn * 64 + fn * 8) >> 3;        // 16B chunk along n
                    uint32_t bd = sb + 16384 + krow * 256 + ((chunkN ^ (krow & 7)) << 4);
                    asm volatile("ldmatrix.sync.aligned.m8n8.x2.trans.shared.b16 {%0,%1}, [%2];\n"
                                 : "=r"(b[fn][0]), "=r"(b[fn][1])
                                 : "r"(bd));
                }
            }
            #pragma unroll
            for (int fm = 0; fm < 4; fm++)
                #pragma unroll
                for (int fn = 0; fn < 8; fn++)
                    asm volatile(
                        "mma.sync.aligned.m16n8k16.row.col.f32.f16.f16.f32 "
                        "{%0,%1,%2,%3}, {%4,%5,%6,%7}, {%8,%9}, {%0,%1,%2,%3};\n"
                        : "+f"(acc[fm][fn][0]), "+f"(acc[fm][fn][1]),
                          "+f"(acc[fm][fn][2]), "+f"(acc[fm][fn][3])
                        : "r"(a[fm][0]), "r"(a[fm][1]), "r"(a[fm][2]), "r"(a[fm][3]),
                          "r"(b[fn][0]), "r"(b[fn][1]));
        }
        __syncthreads();
    }

    // ---------------- epilogues (proven math; n-offset now wn*64, fn<8) ----------------
    const int gq = lane >> 2, cq = lane & 3;
    if constexpr (EPI == 1) {
        #pragma unroll
        for (int fm = 0; fm < 4; fm++)
            #pragma unroll
            for (int fn = 0; fn < 8; fn++) {
                int r0 = mBase + wm * 64 + fm * 16 + gq;
                int c0 = nBase + wn * 64 + fn * 8 + cq * 2;
                float bz0 = bias[c0], bz1 = bias[c0 + 1];
                float v0 = gelu_exact(acc[fm][fn][0] + bz0);
                float v1 = gelu_exact(acc[fm][fn][1] + bz1);
                float v2 = gelu_exact(acc[fm][fn][2] + bz0);
                float v3 = gelu_exact(acc[fm][fn][3] + bz1);
                __half2* o = (__half2*)g_hidh;
                o[((size_t)r0 * DFFDIM + c0) >> 1]       = __floats2half2_rn(v0, v1);
                o[((size_t)(r0 + 8) * DFFDIM + c0) >> 1] = __floats2half2_rn(v2, v3);
            }
    } else {
        #pragma unroll
        for (int fm = 0; fm < 4; fm++) {
            int r0 = mBase + wm * 64 + fm * 16 + gq;
            int r1 = r0 + 8;
            float hp0[4], hp1[4], hr0[16], hr1[16];
            #pragma unroll
            for (int n = 0; n < 4; n++) { hp0[n] = g_hpost[r0 * 4 + n]; hp1[n] = g_hpost[r1 * 4 + n]; }
            #pragma unroll
            for (int i = 0; i < 16; i++) { hr0[i] = g_hres[r0 * 16 + i]; hr1[i] = g_hres[r1 * 16 + i]; }
            #pragma unroll
            for (int fn = 0; fn < 8; fn++) {
                int c0 = nBase + wn * 64 + fn * 8 + cq * 2;
                float bz0 = bias[c0], bz1 = bias[c0 + 1];
                float f0x = acc[fm][fn][0] + bz0, f0y = acc[fm][fn][1] + bz1;
                float f1x = acc[fm][fn][2] + bz0, f1y = acc[fm][fn][3] + bz1;
                float2 x0[4], x1[4];
                #pragma unroll
                for (int j = 0; j < 4; j++) {
                    x0[j] = __half22float2(*(const __half2*)(g_xh + (size_t)r0 * NCDIM + j * CDIM + c0));
                    x1[j] = __half22float2(*(const __half2*)(g_xh + (size_t)r1 * NCDIM + j * CDIM + c0));
                }
                #pragma unroll
                for (int n = 0; n < 4; n++) {
                    float ox = hp0[n] * f0x, oy = hp0[n] * f0y;
                    #pragma unroll
                    for (int j = 0; j < 4; j++) {
                        ox += hr0[n * 4 + j] * x0[j].x;
                        oy += hr0[n * 4 + j] * x0[j].y;
                    }
                    *(float2*)(out + ((size_t)r0 * 4 + n) * CDIM + c0) = make_float2(ox, oy);
                }
                #pragma unroll
                for (int n = 0; n < 4; n++) {
                    float ox = hp1[n] * f1x, oy = hp1[n] * f1y;
                    #pragma unroll
                    for (int j = 0; j < 4; j++) {
                        ox += hr1[n * 4 + j] * x1[j].x;
                        oy += hr1[n * 4 + j] * x1[j].y;
                    }
                    *(float2*)(out + ((size_t)r1 * 4 + n) * CDIM + c0) = make_float2(ox, oy);
                }
            }
        }
    }
}

// ---------------- launch ----------------
extern "C" void kernel_launch(void* const* d_in, const int* in_sizes, int n_in,
                              void* d_out, int out_size) {
    const float* x     = (const float*)d_in[0];
    const float* phi   = (const float*)d_in[1];
    const float* b     = (const float*)d_in[2];
    const float* apre  = (const float*)d_in[3];
    const float* apost = (const float*)d_in[4];
    const float* ares  = (const float*)d_in[5];
    const float* W1    = (const float*)d_in[6];
    const float* b1    = (const float*)d_in[7];
    const float* W2    = (const float*)d_in[8];
    const float* b2    = (const float*)d_in[9];
    float* out = (float*)d_out;

    const int dyn_smem = HP_STAGES * HP_STG_BYTES;   // 96 KB
    cudaFuncSetAttribute(gemm_hp<CDIM, 1>,  cudaFuncAttributeMaxDynamicSharedMemorySize, dyn_smem);
    cudaFuncSetAttribute(gemm_hp<NCDIM, 2>, cudaFuncAttributeMaxDynamicSharedMemorySize, dyn_smem);

    sumsq_convert_kernel<<<TOK / 8, 256>>>(x, phi);
    mix_routing_conv_kernel<<<MIXBLKS + CONVBLKS, 128>>>(W1, W2, b, apre, apost, ares);
    xin_kernel<<<TOK * 384 / 256, 256>>>();
    gemm_hp<CDIM, 1><<<dim3(DFFDIM / 128, TOK / 128), HP_THREADS, dyn_smem>>>(b1, nullptr);
    gemm_hp<NCDIM, 2><<<dim3(CDIM / 128, TOK / 128), HP_THREADS, dyn_smem>>>(b2, out);
}